// round 2
// baseline (speedup 1.0000x reference)
#include <cuda_runtime.h>
#include <math_constants.h>

// Scratch for the K|V projections: [B*N, 256] fp32, K in cols 0..127, V in 128..255.
// 8*2048*256*4 = 16 MB.
static __device__ __align__(16) float g_KV[8 * 2048 * 256];

// ---------------------------------------------------------------------------
// Kernel 1: KV projection GEMM.
//   C[m][j] = sum_k x[m][k] * W[j][k] + bias[j],  W = [w_k ; w_v] (256 x 1024)
//   M = 16384, Ncols = 256, K = 1024.
// 64x64 output tile per block, 256 threads, 4x4 microtile, K-tile = 32.
// Columns owned as j = j0 + jj*16 + tx  -> conflict-free smem loads.
// ---------------------------------------------------------------------------
__global__ __launch_bounds__(256) void kv_gemm_kernel(
    const float* __restrict__ x,
    const float* __restrict__ wk, const float* __restrict__ bk,
    const float* __restrict__ wv, const float* __restrict__ bv)
{
    constexpr int BK  = 32;
    constexpr int PAD = 36;                 // row stride (floats); 36 % 32 == 4 -> stride-4 bank walk
    __shared__ __align__(16) float As[64 * PAD];
    __shared__ __align__(16) float Bs[64 * PAD];

    const int m0  = blockIdx.x * 64;
    const int j0  = blockIdx.y * 64;
    const int tid = threadIdx.x;
    const int ty  = tid >> 4;               // 0..15  (row group)
    const int tx  = tid & 15;               // 0..15  (col group)

    float acc[4][4] = {};

    for (int k0 = 0; k0 < 1024; k0 += BK) {
        __syncthreads();
        // Load A (64x32) and B (64x32) tiles, float4-coalesced, 2 float4 each per array.
        #pragma unroll
        for (int t = 0; t < 2; ++t) {
            int e  = tid + t * 256;         // 0..511 float4 slots
            int r  = e >> 3;                // 0..63
            int c4 = e & 7;                 // 0..7  (float4 within 32 floats)
            float4 av = *reinterpret_cast<const float4*>(
                x + (size_t)(m0 + r) * 1024 + k0 + c4 * 4);
            *reinterpret_cast<float4*>(As + r * PAD + c4 * 4) = av;

            int j = j0 + r;
            const float* wrow = (j < 128) ? (wk + (size_t)j * 1024)
                                          : (wv + (size_t)(j - 128) * 1024);
            float4 bv4 = *reinterpret_cast<const float4*>(wrow + k0 + c4 * 4);
            *reinterpret_cast<float4*>(Bs + r * PAD + c4 * 4) = bv4;
        }
        __syncthreads();

        #pragma unroll
        for (int d4 = 0; d4 < BK / 4; ++d4) {
            float4 a[4], b[4];
            #pragma unroll
            for (int ii = 0; ii < 4; ++ii)
                a[ii] = *reinterpret_cast<const float4*>(As + (ty * 4 + ii) * PAD + d4 * 4);
            #pragma unroll
            for (int jj = 0; jj < 4; ++jj)
                b[jj] = *reinterpret_cast<const float4*>(Bs + (jj * 16 + tx) * PAD + d4 * 4);
            #pragma unroll
            for (int ii = 0; ii < 4; ++ii)
                #pragma unroll
                for (int jj = 0; jj < 4; ++jj) {
                    acc[ii][jj] += a[ii].x * b[jj].x;
                    acc[ii][jj] += a[ii].y * b[jj].y;
                    acc[ii][jj] += a[ii].z * b[jj].z;
                    acc[ii][jj] += a[ii].w * b[jj].w;
                }
        }
    }

    // Epilogue: add bias, store to g_KV.
    #pragma unroll
    for (int jj = 0; jj < 4; ++jj) {
        int j = j0 + jj * 16 + tx;
        float bias = (j < 128) ? bk[j] : bv[j - 128];
        #pragma unroll
        for (int ii = 0; ii < 4; ++ii) {
            int m = m0 + ty * 4 + ii;
            g_KV[(size_t)m * 256 + j] = acc[ii][jj] + bias;
        }
    }
}

// ---------------------------------------------------------------------------
// Kernel 2: fused flash-style attention (no 128 MB logits materialization).
//   logits[n][m] = K[n] . V[m] / sqrt(128);  out = softmax(logits) @ V
// One block per (batch, 64-query tile). Online softmax over 32 key tiles of 64.
// Thread (ty,tx): S microtile rows ty*4+ii, cols jj*16+tx; O cols cc*16+tx.
// smem: Kq[64][132] + Vt[64][132] + Ps[64][68] = 84992 B (dynamic).
// ---------------------------------------------------------------------------
__global__ __launch_bounds__(256) void attn_kernel(float* __restrict__ out)
{
    constexpr int PAD  = 132;               // 132 % 32 == 4 -> conflict-free patterns
    constexpr int PPAD = 68;
    extern __shared__ __align__(16) float sm[];
    float* Kq = sm;                         // 64 * 132
    float* Vt = Kq + 64 * PAD;              // 64 * 132
    float* Ps = Vt + 64 * PAD;              // 64 * 68

    const int b   = blockIdx.y;
    const int m0  = blockIdx.x * 64;
    const float* KB = g_KV + (size_t)b * 2048 * 256;
    const int tid = threadIdx.x;
    const int ty  = tid >> 4;
    const int tx  = tid & 15;
    const float scale = 0.088388347648318447f;   // 1/sqrt(128)

    // Load this block's 64 K rows (queries of the K@V^T product).
    #pragma unroll
    for (int t = 0; t < 8; ++t) {
        int e  = tid + t * 256;             // 2048 float4 slots
        int r  = e >> 5;                    // 0..63
        int c4 = e & 31;                    // 0..31
        float4 v = *reinterpret_cast<const float4*>(
            KB + (size_t)(m0 + r) * 256 + c4 * 4);
        *reinterpret_cast<float4*>(Kq + r * PAD + c4 * 4) = v;
    }

    float o[4][8] = {};
    float mrow[4], lrow[4];
    #pragma unroll
    for (int ii = 0; ii < 4; ++ii) { mrow[ii] = -CUDART_INF_F; lrow[ii] = 0.f; }

    for (int n0 = 0; n0 < 2048; n0 += 64) {
        __syncthreads();   // previous PV done (and first iter: Kq load done)
        // Load V tile [64][128]
        #pragma unroll
        for (int t = 0; t < 8; ++t) {
            int e  = tid + t * 256;
            int r  = e >> 5;
            int c4 = e & 31;
            float4 v = *reinterpret_cast<const float4*>(
                KB + (size_t)(n0 + r) * 256 + 128 + c4 * 4);
            *reinterpret_cast<float4*>(Vt + r * PAD + c4 * 4) = v;
        }
        __syncthreads();

        // ---- S = scale * Kq . Vt^T  (64x64, 4x4 per thread) ----
        float s[4][4] = {};
        #pragma unroll
        for (int d4 = 0; d4 < 32; ++d4) {
            float4 a[4], bb[4];
            #pragma unroll
            for (int ii = 0; ii < 4; ++ii)
                a[ii] = *reinterpret_cast<const float4*>(Kq + (ty * 4 + ii) * PAD + d4 * 4);
            #pragma unroll
            for (int jj = 0; jj < 4; ++jj)
                bb[jj] = *reinterpret_cast<const float4*>(Vt + (jj * 16 + tx) * PAD + d4 * 4);
            #pragma unroll
            for (int ii = 0; ii < 4; ++ii)
                #pragma unroll
                for (int jj = 0; jj < 4; ++jj) {
                    s[ii][jj] += a[ii].x * bb[jj].x;
                    s[ii][jj] += a[ii].y * bb[jj].y;
                    s[ii][jj] += a[ii].z * bb[jj].z;
                    s[ii][jj] += a[ii].w * bb[jj].w;
                }
        }

        // ---- online softmax update (rows owned by the 16-lane tx group) ----
        #pragma unroll
        for (int ii = 0; ii < 4; ++ii) {
            #pragma unroll
            for (int jj = 0; jj < 4; ++jj) s[ii][jj] *= scale;

            float tmax = fmaxf(fmaxf(s[ii][0], s[ii][1]), fmaxf(s[ii][2], s[ii][3]));
            #pragma unroll
            for (int off = 8; off > 0; off >>= 1)
                tmax = fmaxf(tmax, __shfl_xor_sync(0xffffffffu, tmax, off));

            float mnew  = fmaxf(mrow[ii], tmax);
            float alpha = __expf(mrow[ii] - mnew);
            mrow[ii] = mnew;

            float p[4], psum = 0.f;
            #pragma unroll
            for (int jj = 0; jj < 4; ++jj) {
                p[jj] = __expf(s[ii][jj] - mnew);
                psum += p[jj];
            }
            #pragma unroll
            for (int off = 8; off > 0; off >>= 1)
                psum += __shfl_xor_sync(0xffffffffu, psum, off);

            lrow[ii] = lrow[ii] * alpha + psum;
            #pragma unroll
            for (int cc = 0; cc < 8; ++cc) o[ii][cc] *= alpha;

            #pragma unroll
            for (int jj = 0; jj < 4; ++jj)
                Ps[(ty * 4 + ii) * PPAD + jj * 16 + tx] = p[jj];
        }
        __syncthreads();

        // ---- O += Ps @ Vt  (64x128, cols cc*16+tx) ----
        #pragma unroll 4
        for (int j = 0; j < 64; ++j) {
            float pv[4];
            #pragma unroll
            for (int ii = 0; ii < 4; ++ii)
                pv[ii] = Ps[(ty * 4 + ii) * PPAD + j];
            float vv[8];
            #pragma unroll
            for (int cc = 0; cc < 8; ++cc)
                vv[cc] = Vt[j * PAD + cc * 16 + tx];
            #pragma unroll
            for (int ii = 0; ii < 4; ++ii)
                #pragma unroll
                for (int cc = 0; cc < 8; ++cc)
                    o[ii][cc] += pv[ii] * vv[cc];
        }
    }

    // ---- normalize and write out [B,N,128] ----
    #pragma unroll
    for (int ii = 0; ii < 4; ++ii) {
        float inv = 1.f / lrow[ii];
        int m = m0 + ty * 4 + ii;
        float* orow = out + ((size_t)b * 2048 + m) * 128;
        #pragma unroll
        for (int cc = 0; cc < 8; ++cc)
            orow[cc * 16 + tx] = o[ii][cc] * inv;
    }
}

// ---------------------------------------------------------------------------
// Launch. Inputs (metadata order): x, w_q, b_q, w_k, b_k, w_v, b_v.
// w_q/b_q are unused by the reference output.
// ---------------------------------------------------------------------------
extern "C" void kernel_launch(void* const* d_in, const int* in_sizes, int n_in,
                              void* d_out, int out_size)
{
    const float* x  = (const float*)d_in[0];
    const float* wk = (const float*)d_in[3];
    const float* bk = (const float*)d_in[4];
    const float* wv = (const float*)d_in[5];
    const float* bv = (const float*)d_in[6];
    float* out = (float*)d_out;

    (void)in_sizes; (void)n_in; (void)out_size;

    const int ATTN_SMEM = (64 * 132 * 2 + 64 * 68) * 4;   // 84992 B
    cudaFuncSetAttribute(attn_kernel,
                         cudaFuncAttributeMaxDynamicSharedMemorySize, ATTN_SMEM);

    kv_gemm_kernel<<<dim3(256, 4), 256>>>(x, wk, bk, wv, bv);
    attn_kernel<<<dim3(32, 8), 256, ATTN_SMEM>>>(out);
}

// round 3
// speedup vs baseline: 2.1938x; 2.1938x over previous
#include <cuda_runtime.h>
#include <math_constants.h>
#include <cstdint>

// K|V projections, pre-rounded to tf32: [B*N, 256], K cols 0..127, V cols 128..255.
static __device__ __align__(16) float g_KV[8 * 2048 * 256];

// ---------------------------------------------------------------------------
// helpers
// ---------------------------------------------------------------------------
__device__ __forceinline__ float tf32_rna(float v) {
    uint32_t r; asm("cvt.rna.tf32.f32 %0, %1;" : "=r"(r) : "f"(v));
    return __uint_as_float(r);
}

__device__ __forceinline__ void mma8(float c[4],
                                     uint32_t a0, uint32_t a1, uint32_t a2, uint32_t a3,
                                     uint32_t b0, uint32_t b1) {
    asm volatile(
        "mma.sync.aligned.m16n8k8.row.col.f32.tf32.tf32.f32 "
        "{%0,%1,%2,%3}, {%4,%5,%6,%7}, {%8,%9}, {%0,%1,%2,%3};\n"
        : "+f"(c[0]), "+f"(c[1]), "+f"(c[2]), "+f"(c[3])
        : "r"(a0), "r"(a1), "r"(a2), "r"(a3), "r"(b0), "r"(b1));
}

__device__ __forceinline__ void cp16(uint32_t dst, const float* src) {
    asm volatile("cp.async.cg.shared.global [%0], [%1], 16;\n" :: "r"(dst), "l"(src));
}
__device__ __forceinline__ void cp_commit() { asm volatile("cp.async.commit_group;\n"); }
__device__ __forceinline__ void cp_wait0()  { asm volatile("cp.async.wait_group 0;\n"); }

// ---------------------------------------------------------------------------
// Kernel 1: KV projection, 3xTF32 tensor-core GEMM.
//   C[16384 x 256] = X[16384 x 1024] . W^T + bias,  W = [w_k ; w_v]
// Block tile 128x64, BK=32, 8 warps, warp tile 32x32 (2 m-tiles x 4 n-tiles).
// X/W split into tf32 hi+lo at smem-fill time; 3 mma passes per product.
// Output stored pre-rounded to tf32.
// ---------------------------------------------------------------------------
__global__ __launch_bounds__(256) void kv_gemm_kernel(
    const float* __restrict__ x,
    const float* __restrict__ wk, const float* __restrict__ bk,
    const float* __restrict__ wv, const float* __restrict__ bv)
{
    constexpr int PAD = 36;                 // 36 % 32 == 4 -> conflict-free frag loads
    extern __shared__ float smem[];
    float* Xh = smem;                       // 128*36
    float* Xl = Xh + 128 * PAD;
    float* Wh = Xl + 128 * PAD;             // 64*36
    float* Wl = Wh + 64 * PAD;

    const int m0 = blockIdx.x * 128;
    const int j0 = blockIdx.y * 64;
    const int tid  = threadIdx.x;
    const int lane = tid & 31;
    const int w    = tid >> 5;
    const int wm   = w & 3;                 // warp m position (0..3)
    const int wn   = w >> 2;                // warp n position (0..1)
    const int g    = lane >> 2;             // groupID
    const int t    = lane & 3;              // threadID_in_group

    float4 px[4], pw[2];
    float acc[2][4][4] = {};

    // prologue fetch (k0 = 0)
    #pragma unroll
    for (int i = 0; i < 4; ++i) {
        int e = tid + i * 256, r = e >> 3, c4 = e & 7;
        px[i] = *reinterpret_cast<const float4*>(x + (size_t)(m0 + r) * 1024 + c4 * 4);
    }
    #pragma unroll
    for (int i = 0; i < 2; ++i) {
        int e = tid + i * 256, r = e >> 3, c4 = e & 7;
        int j = j0 + r;
        const float* wr = (j < 128) ? wk + (size_t)j * 1024 : wv + (size_t)(j - 128) * 1024;
        pw[i] = *reinterpret_cast<const float4*>(wr + c4 * 4);
    }

    for (int kt = 0; kt < 32; ++kt) {
        __syncthreads();
        // split + store staged tile
        #pragma unroll
        for (int i = 0; i < 4; ++i) {
            int e = tid + i * 256, r = e >> 3, c4 = e & 7;
            float4 h, l;
            h.x = tf32_rna(px[i].x); l.x = tf32_rna(px[i].x - h.x);
            h.y = tf32_rna(px[i].y); l.y = tf32_rna(px[i].y - h.y);
            h.z = tf32_rna(px[i].z); l.z = tf32_rna(px[i].z - h.z);
            h.w = tf32_rna(px[i].w); l.w = tf32_rna(px[i].w - h.w);
            *reinterpret_cast<float4*>(Xh + r * PAD + c4 * 4) = h;
            *reinterpret_cast<float4*>(Xl + r * PAD + c4 * 4) = l;
        }
        #pragma unroll
        for (int i = 0; i < 2; ++i) {
            int e = tid + i * 256, r = e >> 3, c4 = e & 7;
            float4 h, l;
            h.x = tf32_rna(pw[i].x); l.x = tf32_rna(pw[i].x - h.x);
            h.y = tf32_rna(pw[i].y); l.y = tf32_rna(pw[i].y - h.y);
            h.z = tf32_rna(pw[i].z); l.z = tf32_rna(pw[i].z - h.z);
            h.w = tf32_rna(pw[i].w); l.w = tf32_rna(pw[i].w - h.w);
            *reinterpret_cast<float4*>(Wh + r * PAD + c4 * 4) = h;
            *reinterpret_cast<float4*>(Wl + r * PAD + c4 * 4) = l;
        }
        // prefetch next tile while computing
        if (kt < 31) {
            int k0 = (kt + 1) * 32;
            #pragma unroll
            for (int i = 0; i < 4; ++i) {
                int e = tid + i * 256, r = e >> 3, c4 = e & 7;
                px[i] = *reinterpret_cast<const float4*>(x + (size_t)(m0 + r) * 1024 + k0 + c4 * 4);
            }
            #pragma unroll
            for (int i = 0; i < 2; ++i) {
                int e = tid + i * 256, r = e >> 3, c4 = e & 7;
                int j = j0 + r;
                const float* wr = (j < 128) ? wk + (size_t)j * 1024 : wv + (size_t)(j - 128) * 1024;
                pw[i] = *reinterpret_cast<const float4*>(wr + k0 + c4 * 4);
            }
        }
        __syncthreads();

        #pragma unroll
        for (int ks = 0; ks < 4; ++ks) {
            const int k = ks * 8;
            uint32_t ah[2][4], al[2][4];
            #pragma unroll
            for (int mt = 0; mt < 2; ++mt) {
                int rb = wm * 32 + mt * 16;
                ah[mt][0] = __float_as_uint(Xh[(rb + g    ) * PAD + k + t    ]);
                ah[mt][1] = __float_as_uint(Xh[(rb + g + 8) * PAD + k + t    ]);
                ah[mt][2] = __float_as_uint(Xh[(rb + g    ) * PAD + k + t + 4]);
                ah[mt][3] = __float_as_uint(Xh[(rb + g + 8) * PAD + k + t + 4]);
                al[mt][0] = __float_as_uint(Xl[(rb + g    ) * PAD + k + t    ]);
                al[mt][1] = __float_as_uint(Xl[(rb + g + 8) * PAD + k + t    ]);
                al[mt][2] = __float_as_uint(Xl[(rb + g    ) * PAD + k + t + 4]);
                al[mt][3] = __float_as_uint(Xl[(rb + g + 8) * PAD + k + t + 4]);
            }
            #pragma unroll
            for (int nt = 0; nt < 4; ++nt) {
                int cb = wn * 32 + nt * 8;
                uint32_t bh0 = __float_as_uint(Wh[(cb + g) * PAD + k + t    ]);
                uint32_t bh1 = __float_as_uint(Wh[(cb + g) * PAD + k + t + 4]);
                uint32_t bl0 = __float_as_uint(Wl[(cb + g) * PAD + k + t    ]);
                uint32_t bl1 = __float_as_uint(Wl[(cb + g) * PAD + k + t + 4]);
                #pragma unroll
                for (int mt = 0; mt < 2; ++mt) {
                    mma8(acc[mt][nt], al[mt][0], al[mt][1], al[mt][2], al[mt][3], bh0, bh1);
                    mma8(acc[mt][nt], ah[mt][0], ah[mt][1], ah[mt][2], ah[mt][3], bl0, bl1);
                    mma8(acc[mt][nt], ah[mt][0], ah[mt][1], ah[mt][2], ah[mt][3], bh0, bh1);
                }
            }
        }
    }

    // epilogue: + bias, round to tf32, store
    #pragma unroll
    for (int mt = 0; mt < 2; ++mt) {
        int r0 = m0 + wm * 32 + mt * 16 + g;
        int r1 = r0 + 8;
        #pragma unroll
        for (int nt = 0; nt < 4; ++nt) {
            int col = j0 + wn * 32 + nt * 8 + 2 * t;
            float b0 = (col     < 128) ? bk[col]       : bv[col - 128];
            float b1 = (col + 1 < 128) ? bk[col + 1]   : bv[col + 1 - 128];
            float2 v0 = { tf32_rna(acc[mt][nt][0] + b0), tf32_rna(acc[mt][nt][1] + b1) };
            float2 v1 = { tf32_rna(acc[mt][nt][2] + b0), tf32_rna(acc[mt][nt][3] + b1) };
            *reinterpret_cast<float2*>(g_KV + (size_t)r0 * 256 + col) = v0;
            *reinterpret_cast<float2*>(g_KV + (size_t)r1 * 256 + col) = v1;
        }
    }
}

// ---------------------------------------------------------------------------
// Kernel 2: fused flash attention, tf32 tensor cores.
// Block: 128 queries, 4 warps (warp = 32 rows = 2 m-tiles), key tiles of 64.
// cp.async double-buffered V. O accumulators in registers (128/thread).
// ---------------------------------------------------------------------------
__global__ __launch_bounds__(128, 1) void attn_kernel(float* __restrict__ out)
{
    constexpr int PAD  = 132;               // 132 % 32 == 4
    constexpr int PPAD = 68;                // 68 % 32 == 4
    extern __shared__ float sm[];
    float* Kq = sm;                         // 128 * 132
    float* Vb = Kq + 128 * PAD;             // 2 * 64 * 132
    float* Ps = Vb + 2 * 64 * PAD;          // 128 * 68

    const int b  = blockIdx.y;
    const int q0 = blockIdx.x * 128;
    const float* KB = g_KV + (size_t)b * 2048 * 256;
    const int tid  = threadIdx.x;
    const int lane = tid & 31;
    const int w    = tid >> 5;
    const int g    = lane >> 2;
    const int t    = lane & 3;
    const float scale = 0.088388347648318447f;   // 1/sqrt(128)

    const uint32_t sKq = (uint32_t)__cvta_generic_to_shared(Kq);
    const uint32_t sV  = (uint32_t)__cvta_generic_to_shared(Vb);

    // prologue: Kq (32 cp16/thread) + V tile 0 (16 cp16/thread)
    #pragma unroll
    for (int i = 0; i < 32; ++i) {
        int slot = tid + i * 128, r = slot >> 5, c4 = slot & 31;
        cp16(sKq + (uint32_t)(r * PAD + c4 * 4) * 4, KB + (size_t)(q0 + r) * 256 + c4 * 4);
    }
    #pragma unroll
    for (int i = 0; i < 16; ++i) {
        int slot = tid + i * 128, r = slot >> 5, c4 = slot & 31;
        cp16(sV + (uint32_t)(r * PAD + c4 * 4) * 4, KB + (size_t)r * 256 + 128 + c4 * 4);
    }
    cp_commit();

    float o[2][16][4] = {};
    float mrow[2][2], lrow[2][2];
    #pragma unroll
    for (int mt = 0; mt < 2; ++mt) {
        mrow[mt][0] = -CUDART_INF_F; mrow[mt][1] = -CUDART_INF_F;
        lrow[mt][0] = 0.f;           lrow[mt][1] = 0.f;
    }

    for (int kt = 0; kt < 32; ++kt) {
        cp_wait0();
        __syncthreads();
        if (kt < 31) {
            int n0 = (kt + 1) * 64;
            uint32_t dst = sV + (uint32_t)(((kt + 1) & 1) * 64 * PAD) * 4;
            #pragma unroll
            for (int i = 0; i < 16; ++i) {
                int slot = tid + i * 128, r = slot >> 5, c4 = slot & 31;
                cp16(dst + (uint32_t)(r * PAD + c4 * 4) * 4,
                     KB + (size_t)(n0 + r) * 256 + 128 + c4 * 4);
            }
            cp_commit();
        }
        const float* Vt = Vb + (kt & 1) * 64 * PAD;

        // ---- S = Kq . V^T, softmax, write P (per m-tile to cap registers) ----
        #pragma unroll
        for (int mt = 0; mt < 2; ++mt) {
            const int rb = w * 32 + mt * 16;
            float s[8][4] = {};
            #pragma unroll 4
            for (int ks = 0; ks < 16; ++ks) {
                const int k = ks * 8;
                uint32_t a0 = __float_as_uint(Kq[(rb + g    ) * PAD + k + t    ]);
                uint32_t a1 = __float_as_uint(Kq[(rb + g + 8) * PAD + k + t    ]);
                uint32_t a2 = __float_as_uint(Kq[(rb + g    ) * PAD + k + t + 4]);
                uint32_t a3 = __float_as_uint(Kq[(rb + g + 8) * PAD + k + t + 4]);
                #pragma unroll
                for (int nt = 0; nt < 8; ++nt) {
                    uint32_t b0 = __float_as_uint(Vt[(nt * 8 + g) * PAD + k + t    ]);
                    uint32_t b1 = __float_as_uint(Vt[(nt * 8 + g) * PAD + k + t + 4]);
                    mma8(s[nt], a0, a1, a2, a3, b0, b1);
                }
            }
            // scale
            #pragma unroll
            for (int nt = 0; nt < 8; ++nt)
                #pragma unroll
                for (int c = 0; c < 4; ++c) s[nt][c] *= scale;

            // row maxima (row0 = g: c0,c1 ; row1 = g+8: c2,c3)
            float mx0 = -CUDART_INF_F, mx1 = -CUDART_INF_F;
            #pragma unroll
            for (int nt = 0; nt < 8; ++nt) {
                mx0 = fmaxf(mx0, fmaxf(s[nt][0], s[nt][1]));
                mx1 = fmaxf(mx1, fmaxf(s[nt][2], s[nt][3]));
            }
            mx0 = fmaxf(mx0, __shfl_xor_sync(0xffffffffu, mx0, 1));
            mx0 = fmaxf(mx0, __shfl_xor_sync(0xffffffffu, mx0, 2));
            mx1 = fmaxf(mx1, __shfl_xor_sync(0xffffffffu, mx1, 1));
            mx1 = fmaxf(mx1, __shfl_xor_sync(0xffffffffu, mx1, 2));

            float mn0 = fmaxf(mrow[mt][0], mx0);
            float mn1 = fmaxf(mrow[mt][1], mx1);
            float al0 = __expf(mrow[mt][0] - mn0);
            float al1 = __expf(mrow[mt][1] - mn1);
            mrow[mt][0] = mn0; mrow[mt][1] = mn1;

            float sum0 = 0.f, sum1 = 0.f;
            #pragma unroll
            for (int nt = 0; nt < 8; ++nt) {
                float p00 = __expf(s[nt][0] - mn0);
                float p01 = __expf(s[nt][1] - mn0);
                float p10 = __expf(s[nt][2] - mn1);
                float p11 = __expf(s[nt][3] - mn1);
                sum0 += p00 + p01;
                sum1 += p10 + p11;
                float2 w0 = { tf32_rna(p00), tf32_rna(p01) };
                float2 w1 = { tf32_rna(p10), tf32_rna(p11) };
                *reinterpret_cast<float2*>(Ps + (rb + g    ) * PPAD + nt * 8 + 2 * t) = w0;
                *reinterpret_cast<float2*>(Ps + (rb + g + 8) * PPAD + nt * 8 + 2 * t) = w1;
            }
            sum0 += __shfl_xor_sync(0xffffffffu, sum0, 1);
            sum0 += __shfl_xor_sync(0xffffffffu, sum0, 2);
            sum1 += __shfl_xor_sync(0xffffffffu, sum1, 1);
            sum1 += __shfl_xor_sync(0xffffffffu, sum1, 2);
            lrow[mt][0] = lrow[mt][0] * al0 + sum0;
            lrow[mt][1] = lrow[mt][1] * al1 + sum1;

            #pragma unroll
            for (int dt = 0; dt < 16; ++dt) {
                o[mt][dt][0] *= al0; o[mt][dt][1] *= al0;
                o[mt][dt][2] *= al1; o[mt][dt][3] *= al1;
            }
        }
        __syncwarp();

        // ---- O += P . V  (B frags = transposed-address reads of Vt) ----
        #pragma unroll 2
        for (int ks = 0; ks < 8; ++ks) {
            const int k = ks * 8;
            uint32_t pa[2][4];
            #pragma unroll
            for (int mt = 0; mt < 2; ++mt) {
                int rb = w * 32 + mt * 16;
                pa[mt][0] = __float_as_uint(Ps[(rb + g    ) * PPAD + k + t    ]);
                pa[mt][1] = __float_as_uint(Ps[(rb + g + 8) * PPAD + k + t    ]);
                pa[mt][2] = __float_as_uint(Ps[(rb + g    ) * PPAD + k + t + 4]);
                pa[mt][3] = __float_as_uint(Ps[(rb + g + 8) * PPAD + k + t + 4]);
            }
            #pragma unroll
            for (int dt = 0; dt < 16; ++dt) {
                uint32_t b0 = __float_as_uint(Vt[(k + t    ) * PAD + dt * 8 + g]);
                uint32_t b1 = __float_as_uint(Vt[(k + t + 4) * PAD + dt * 8 + g]);
                mma8(o[0][dt], pa[0][0], pa[0][1], pa[0][2], pa[0][3], b0, b1);
                mma8(o[1][dt], pa[1][0], pa[1][1], pa[1][2], pa[1][3], b0, b1);
            }
        }
    }

    // ---- epilogue: normalize, write out [B, N, 128] ----
    #pragma unroll
    for (int mt = 0; mt < 2; ++mt) {
        float inv0 = 1.f / lrow[mt][0];
        float inv1 = 1.f / lrow[mt][1];
        int r0 = q0 + w * 32 + mt * 16 + g;
        int r1 = r0 + 8;
        float* o0 = out + ((size_t)b * 2048 + r0) * 128;
        float* o1 = out + ((size_t)b * 2048 + r1) * 128;
        #pragma unroll
        for (int dt = 0; dt < 16; ++dt) {
            float2 v0 = { o[mt][dt][0] * inv0, o[mt][dt][1] * inv0 };
            float2 v1 = { o[mt][dt][2] * inv1, o[mt][dt][3] * inv1 };
            *reinterpret_cast<float2*>(o0 + dt * 8 + 2 * t) = v0;
            *reinterpret_cast<float2*>(o1 + dt * 8 + 2 * t) = v1;
        }
    }
}

// ---------------------------------------------------------------------------
// Launch. Inputs: x, w_q, b_q, w_k, b_k, w_v, b_v (w_q/b_q unused).
// ---------------------------------------------------------------------------
extern "C" void kernel_launch(void* const* d_in, const int* in_sizes, int n_in,
                              void* d_out, int out_size)
{
    const float* x  = (const float*)d_in[0];
    const float* wk = (const float*)d_in[3];
    const float* bk = (const float*)d_in[4];
    const float* wv = (const float*)d_in[5];
    const float* bv = (const float*)d_in[6];
    float* out = (float*)d_out;
    (void)in_sizes; (void)n_in; (void)out_size;

    const int GEMM_SMEM = (128 * 36 * 2 + 64 * 36 * 2) * 4;         // 55296 B
    const int ATTN_SMEM = (128 * 132 + 2 * 64 * 132 + 128 * 68) * 4; // 169984 B
    cudaFuncSetAttribute(kv_gemm_kernel,
                         cudaFuncAttributeMaxDynamicSharedMemorySize, GEMM_SMEM);
    cudaFuncSetAttribute(attn_kernel,
                         cudaFuncAttributeMaxDynamicSharedMemorySize, ATTN_SMEM);

    kv_gemm_kernel<<<dim3(128, 4), 256, GEMM_SMEM>>>(x, wk, bk, wv, bv);
    attn_kernel<<<dim3(16, 8), 128, ATTN_SMEM>>>(out);
}

// round 4
// speedup vs baseline: 2.7816x; 1.2679x over previous
#include <cuda_runtime.h>
#include <math_constants.h>
#include <cstdint>

// K|V projections (tf32-rounded): [B*N, 256], K cols 0..127, V cols 128..255.
static __device__ __align__(16) float g_KV[8 * 2048 * 256];
// Split-KV partials: O~ (unnormalized), m, l per kv-half.
static __device__ __align__(16) float g_PO[2 * 8 * 2048 * 128];
static __device__ float g_Pm[2 * 8 * 2048];
static __device__ float g_Pl[2 * 8 * 2048];

// ---------------------------------------------------------------------------
// helpers
// ---------------------------------------------------------------------------
__device__ __forceinline__ float tf32_rna(float v) {
    uint32_t r; asm("cvt.rna.tf32.f32 %0, %1;" : "=r"(r) : "f"(v));
    return __uint_as_float(r);
}

__device__ __forceinline__ void mma8(float c[4],
                                     uint32_t a0, uint32_t a1, uint32_t a2, uint32_t a3,
                                     uint32_t b0, uint32_t b1) {
    asm volatile(
        "mma.sync.aligned.m16n8k8.row.col.f32.tf32.tf32.f32 "
        "{%0,%1,%2,%3}, {%4,%5,%6,%7}, {%8,%9}, {%0,%1,%2,%3};\n"
        : "+f"(c[0]), "+f"(c[1]), "+f"(c[2]), "+f"(c[3])
        : "r"(a0), "r"(a1), "r"(a2), "r"(a3), "r"(b0), "r"(b1));
}

__device__ __forceinline__ void cp16(uint32_t dst, const float* src) {
    asm volatile("cp.async.cg.shared.global [%0], [%1], 16;\n" :: "r"(dst), "l"(src));
}
__device__ __forceinline__ void cp_commit() { asm volatile("cp.async.commit_group;\n"); }
__device__ __forceinline__ void cp_wait0()  { asm volatile("cp.async.wait_group 0;\n"); }

// XOR swizzle: float index for logical (row, col) in a 128-float-wide tile.
// Guarantees conflict-free mma fragment loads (rows g..g+8 at fixed col).
#define SWI(r, c) ((r) * 128 + ((c) ^ (((r) & 7) << 2)))

// ---------------------------------------------------------------------------
// Kernel 1: KV projection, 2-pass tf32 tensor-core GEMM (W hi/lo compensated).
//   C[16384 x 256] = X . W^T + bias,  W = [w_k ; w_v]
// Block tile 128x64, BK=32, 8 warps (4m x 2n), warp tile 32x32.
// ---------------------------------------------------------------------------
__global__ __launch_bounds__(256, 2) void kv_gemm_kernel(
    const float* __restrict__ x,
    const float* __restrict__ wk, const float* __restrict__ bk,
    const float* __restrict__ wv, const float* __restrict__ bv)
{
    constexpr int PAD = 36;
    extern __shared__ float smem[];
    float* Xh = smem;                       // 128*36
    float* Wh = Xh + 128 * PAD;             // 64*36
    float* Wl = Wh + 64 * PAD;              // 64*36

    const int m0 = blockIdx.x * 128;
    const int j0 = blockIdx.y * 64;
    const int tid  = threadIdx.x;
    const int lane = tid & 31;
    const int w    = tid >> 5;
    const int wm   = w & 3;
    const int wn   = w >> 2;
    const int g    = lane >> 2;
    const int t    = lane & 3;

    float4 px[4], pw[2];
    float acc[2][4][4] = {};

    #pragma unroll
    for (int i = 0; i < 4; ++i) {
        int e = tid + i * 256, r = e >> 3, c4 = e & 7;
        px[i] = *reinterpret_cast<const float4*>(x + (size_t)(m0 + r) * 1024 + c4 * 4);
    }
    #pragma unroll
    for (int i = 0; i < 2; ++i) {
        int e = tid + i * 256, r = e >> 3, c4 = e & 7;
        int j = j0 + r;
        const float* wr = (j < 128) ? wk + (size_t)j * 1024 : wv + (size_t)(j - 128) * 1024;
        pw[i] = *reinterpret_cast<const float4*>(wr + c4 * 4);
    }

    for (int kt = 0; kt < 32; ++kt) {
        __syncthreads();
        #pragma unroll
        for (int i = 0; i < 4; ++i) {
            int e = tid + i * 256, r = e >> 3, c4 = e & 7;
            float4 h;
            h.x = tf32_rna(px[i].x); h.y = tf32_rna(px[i].y);
            h.z = tf32_rna(px[i].z); h.w = tf32_rna(px[i].w);
            *reinterpret_cast<float4*>(Xh + r * PAD + c4 * 4) = h;
        }
        #pragma unroll
        for (int i = 0; i < 2; ++i) {
            int e = tid + i * 256, r = e >> 3, c4 = e & 7;
            float4 h, l;
            h.x = tf32_rna(pw[i].x); l.x = tf32_rna(pw[i].x - h.x);
            h.y = tf32_rna(pw[i].y); l.y = tf32_rna(pw[i].y - h.y);
            h.z = tf32_rna(pw[i].z); l.z = tf32_rna(pw[i].z - h.z);
            h.w = tf32_rna(pw[i].w); l.w = tf32_rna(pw[i].w - h.w);
            *reinterpret_cast<float4*>(Wh + r * PAD + c4 * 4) = h;
            *reinterpret_cast<float4*>(Wl + r * PAD + c4 * 4) = l;
        }
        if (kt < 31) {
            int k0 = (kt + 1) * 32;
            #pragma unroll
            for (int i = 0; i < 4; ++i) {
                int e = tid + i * 256, r = e >> 3, c4 = e & 7;
                px[i] = *reinterpret_cast<const float4*>(x + (size_t)(m0 + r) * 1024 + k0 + c4 * 4);
            }
            #pragma unroll
            for (int i = 0; i < 2; ++i) {
                int e = tid + i * 256, r = e >> 3, c4 = e & 7;
                int j = j0 + r;
                const float* wr = (j < 128) ? wk + (size_t)j * 1024 : wv + (size_t)(j - 128) * 1024;
                pw[i] = *reinterpret_cast<const float4*>(wr + k0 + c4 * 4);
            }
        }
        __syncthreads();

        #pragma unroll
        for (int ks = 0; ks < 4; ++ks) {
            const int k = ks * 8;
            uint32_t ah[2][4];
            #pragma unroll
            for (int mt = 0; mt < 2; ++mt) {
                int rb = wm * 32 + mt * 16;
                ah[mt][0] = __float_as_uint(Xh[(rb + g    ) * PAD + k + t    ]);
                ah[mt][1] = __float_as_uint(Xh[(rb + g + 8) * PAD + k + t    ]);
                ah[mt][2] = __float_as_uint(Xh[(rb + g    ) * PAD + k + t + 4]);
                ah[mt][3] = __float_as_uint(Xh[(rb + g + 8) * PAD + k + t + 4]);
            }
            #pragma unroll
            for (int nt = 0; nt < 4; ++nt) {
                int cb = wn * 32 + nt * 8;
                uint32_t bh0 = __float_as_uint(Wh[(cb + g) * PAD + k + t    ]);
                uint32_t bh1 = __float_as_uint(Wh[(cb + g) * PAD + k + t + 4]);
                uint32_t bl0 = __float_as_uint(Wl[(cb + g) * PAD + k + t    ]);
                uint32_t bl1 = __float_as_uint(Wl[(cb + g) * PAD + k + t + 4]);
                #pragma unroll
                for (int mt = 0; mt < 2; ++mt) {
                    mma8(acc[mt][nt], ah[mt][0], ah[mt][1], ah[mt][2], ah[mt][3], bl0, bl1);
                    mma8(acc[mt][nt], ah[mt][0], ah[mt][1], ah[mt][2], ah[mt][3], bh0, bh1);
                }
            }
        }
    }

    #pragma unroll
    for (int mt = 0; mt < 2; ++mt) {
        int r0 = m0 + wm * 32 + mt * 16 + g;
        int r1 = r0 + 8;
        #pragma unroll
        for (int nt = 0; nt < 4; ++nt) {
            int col = j0 + wn * 32 + nt * 8 + 2 * t;
            float b0 = (col     < 128) ? bk[col]     : bv[col - 128];
            float b1 = (col + 1 < 128) ? bk[col + 1] : bv[col + 1 - 128];
            float2 v0 = { tf32_rna(acc[mt][nt][0] + b0), tf32_rna(acc[mt][nt][1] + b1) };
            float2 v1 = { tf32_rna(acc[mt][nt][2] + b0), tf32_rna(acc[mt][nt][3] + b1) };
            *reinterpret_cast<float2*>(g_KV + (size_t)r0 * 256 + col) = v0;
            *reinterpret_cast<float2*>(g_KV + (size_t)r1 * 256 + col) = v1;
        }
    }
}

// ---------------------------------------------------------------------------
// Kernel 2: fused flash attention, split-KV x2.
// Block: 256 queries, 8 warps (warp = 32 rows = 2 m-tiles), key tiles of 64,
// 1024 keys per CTA. P goes C-frag -> A-frag via shfl (no smem round trip).
// ---------------------------------------------------------------------------
__global__ __launch_bounds__(256, 1) void attn_kernel()
{
    extern __shared__ float sm[];
    float* Kq = sm;                         // 256 x 128 (XOR swizzled)
    float* Vb = sm + 256 * 128;             // 2 x 64 x 128 (XOR swizzled)

    const int q0  = blockIdx.x * 256;
    const int kvi = blockIdx.y;             // 0/1
    const int b   = blockIdx.z;
    const int s0  = kvi * 1024;
    const float* KB = g_KV + (size_t)b * 2048 * 256;
    const int tid  = threadIdx.x;
    const int lane = tid & 31;
    const int w    = tid >> 5;
    const int g    = lane >> 2;
    const int t    = lane & 3;
    const float scale = 0.088388347648318447f;   // 1/sqrt(128)

    const uint32_t sKq = (uint32_t)__cvta_generic_to_shared(Kq);
    const uint32_t sV  = (uint32_t)__cvta_generic_to_shared(Vb);

    // prologue: Kq (256 rows) + V tile 0
    #pragma unroll
    for (int i = 0; i < 32; ++i) {
        int slot = tid + i * 256, r = slot >> 5, c4 = slot & 31;
        cp16(sKq + (uint32_t)SWI(r, c4 * 4) * 4, KB + (size_t)(q0 + r) * 256 + c4 * 4);
    }
    #pragma unroll
    for (int i = 0; i < 8; ++i) {
        int slot = tid + i * 256, r = slot >> 5, c4 = slot & 31;
        cp16(sV + (uint32_t)SWI(r, c4 * 4) * 4, KB + (size_t)(s0 + r) * 256 + 128 + c4 * 4);
    }
    cp_commit();

    float o[2][16][4] = {};
    float mrow[2][2], lrow[2][2];
    #pragma unroll
    for (int mt = 0; mt < 2; ++mt) {
        mrow[mt][0] = -CUDART_INF_F; mrow[mt][1] = -CUDART_INF_F;
        lrow[mt][0] = 0.f;           lrow[mt][1] = 0.f;
    }

    const int rb0 = w * 32;                 // warp's first query row in block

    for (int kt = 0; kt < 16; ++kt) {
        cp_wait0();
        __syncthreads();
        if (kt < 15) {
            int n0 = s0 + (kt + 1) * 64;
            uint32_t dst = sV + (uint32_t)(((kt + 1) & 1) * 64 * 128) * 4;
            #pragma unroll
            for (int i = 0; i < 8; ++i) {
                int slot = tid + i * 256, r = slot >> 5, c4 = slot & 31;
                cp16(dst + (uint32_t)SWI(r, c4 * 4) * 4,
                     KB + (size_t)(n0 + r) * 256 + 128 + c4 * 4);
            }
            cp_commit();
        }
        const float* Vt = Vb + (kt & 1) * 64 * 128;

        // ---- S = Kq . V^T for both m-tiles (B frags loaded once) ----
        float s[2][8][4] = {};
        #pragma unroll
        for (int ks = 0; ks < 16; ++ks) {
            const int k = ks * 8;
            uint32_t a[2][4];
            #pragma unroll
            for (int mt = 0; mt < 2; ++mt) {
                int r0 = rb0 + mt * 16 + g, r1 = r0 + 8;
                a[mt][0] = __float_as_uint(Kq[SWI(r0, k + t    )]);
                a[mt][1] = __float_as_uint(Kq[SWI(r1, k + t    )]);
                a[mt][2] = __float_as_uint(Kq[SWI(r0, k + t + 4)]);
                a[mt][3] = __float_as_uint(Kq[SWI(r1, k + t + 4)]);
            }
            #pragma unroll
            for (int nt = 0; nt < 8; ++nt) {
                int vr = nt * 8 + g;
                uint32_t b0 = __float_as_uint(Vt[SWI(vr, k + t    )]);
                uint32_t b1 = __float_as_uint(Vt[SWI(vr, k + t + 4)]);
                mma8(s[0][nt], a[0][0], a[0][1], a[0][2], a[0][3], b0, b1);
                mma8(s[1][nt], a[1][0], a[1][1], a[1][2], a[1][3], b0, b1);
            }
        }

        // ---- online softmax + C-frag -> A-frag conversion via shfl ----
        uint32_t pa[2][8][4];
        const int src0 = (lane & ~3) | (t >> 1);
        const int src1 = src0 + 2;
        #pragma unroll
        for (int mt = 0; mt < 2; ++mt) {
            #pragma unroll
            for (int nt = 0; nt < 8; ++nt)
                #pragma unroll
                for (int c = 0; c < 4; ++c) s[mt][nt][c] *= scale;

            float mx0 = -CUDART_INF_F, mx1 = -CUDART_INF_F;
            #pragma unroll
            for (int nt = 0; nt < 8; ++nt) {
                mx0 = fmaxf(mx0, fmaxf(s[mt][nt][0], s[mt][nt][1]));
                mx1 = fmaxf(mx1, fmaxf(s[mt][nt][2], s[mt][nt][3]));
            }
            mx0 = fmaxf(mx0, __shfl_xor_sync(0xffffffffu, mx0, 1));
            mx0 = fmaxf(mx0, __shfl_xor_sync(0xffffffffu, mx0, 2));
            mx1 = fmaxf(mx1, __shfl_xor_sync(0xffffffffu, mx1, 1));
            mx1 = fmaxf(mx1, __shfl_xor_sync(0xffffffffu, mx1, 2));

            float mn0 = fmaxf(mrow[mt][0], mx0);
            float mn1 = fmaxf(mrow[mt][1], mx1);
            float al0 = __expf(mrow[mt][0] - mn0);
            float al1 = __expf(mrow[mt][1] - mn1);
            mrow[mt][0] = mn0; mrow[mt][1] = mn1;

            float sum0 = 0.f, sum1 = 0.f;
            #pragma unroll
            for (int nt = 0; nt < 8; ++nt) {
                float p0 = __expf(s[mt][nt][0] - mn0);
                float p1 = __expf(s[mt][nt][1] - mn0);
                float p2 = __expf(s[mt][nt][2] - mn1);
                float p3 = __expf(s[mt][nt][3] - mn1);
                sum0 += p0 + p1;
                sum1 += p2 + p3;
                p0 = tf32_rna(p0); p1 = tf32_rna(p1);
                p2 = tf32_rna(p2); p3 = tf32_rna(p3);
                // redistribute: C-frag (cols 2t,2t+1) -> A-frag (cols t, t+4)
                float x0 = __shfl_sync(0xffffffffu, p0, src0);
                float x1 = __shfl_sync(0xffffffffu, p1, src0);
                float y0 = __shfl_sync(0xffffffffu, p2, src0);
                float y1 = __shfl_sync(0xffffffffu, p3, src0);
                float z0 = __shfl_sync(0xffffffffu, p0, src1);
                float z1 = __shfl_sync(0xffffffffu, p1, src1);
                float u0 = __shfl_sync(0xffffffffu, p2, src1);
                float u1 = __shfl_sync(0xffffffffu, p3, src1);
                pa[mt][nt][0] = __float_as_uint((t & 1) ? x1 : x0);  // (g,   t)
                pa[mt][nt][1] = __float_as_uint((t & 1) ? y1 : y0);  // (g+8, t)
                pa[mt][nt][2] = __float_as_uint((t & 1) ? z1 : z0);  // (g,   t+4)
                pa[mt][nt][3] = __float_as_uint((t & 1) ? u1 : u0);  // (g+8, t+4)
            }
            sum0 += __shfl_xor_sync(0xffffffffu, sum0, 1);
            sum0 += __shfl_xor_sync(0xffffffffu, sum0, 2);
            sum1 += __shfl_xor_sync(0xffffffffu, sum1, 1);
            sum1 += __shfl_xor_sync(0xffffffffu, sum1, 2);
            lrow[mt][0] = lrow[mt][0] * al0 + sum0;
            lrow[mt][1] = lrow[mt][1] * al1 + sum1;

            #pragma unroll
            for (int dt = 0; dt < 16; ++dt) {
                o[mt][dt][0] *= al0; o[mt][dt][1] *= al0;
                o[mt][dt][2] *= al1; o[mt][dt][3] *= al1;
            }
        }

        // ---- O += P . V  (B frags = transposed-address reads of Vt) ----
        #pragma unroll 2
        for (int ks = 0; ks < 8; ++ks) {
            const int k = ks * 8;
            #pragma unroll
            for (int dt = 0; dt < 16; ++dt) {
                int c = dt * 8 + g;
                uint32_t b0 = __float_as_uint(Vt[SWI(k + t,     c)]);
                uint32_t b1 = __float_as_uint(Vt[SWI(k + t + 4, c)]);
                mma8(o[0][dt], pa[0][ks][0], pa[0][ks][1], pa[0][ks][2], pa[0][ks][3], b0, b1);
                mma8(o[1][dt], pa[1][ks][0], pa[1][ks][1], pa[1][ks][2], pa[1][ks][3], b0, b1);
            }
        }
    }

    // ---- epilogue: store unnormalized partial O and (m, l) ----
    const size_t pbase = ((size_t)kvi * 8 + b) * 2048 + q0;
    #pragma unroll
    for (int mt = 0; mt < 2; ++mt) {
        int r0 = rb0 + mt * 16 + g;
        int r1 = r0 + 8;
        float* o0 = g_PO + (pbase + r0) * 128;
        float* o1 = g_PO + (pbase + r1) * 128;
        #pragma unroll
        for (int dt = 0; dt < 16; ++dt) {
            float2 v0 = { o[mt][dt][0], o[mt][dt][1] };
            float2 v1 = { o[mt][dt][2], o[mt][dt][3] };
            *reinterpret_cast<float2*>(o0 + dt * 8 + 2 * t) = v0;
            *reinterpret_cast<float2*>(o1 + dt * 8 + 2 * t) = v1;
        }
        if (t == 0) {
            g_Pm[pbase + r0] = mrow[mt][0];
            g_Pm[pbase + r1] = mrow[mt][1];
            g_Pl[pbase + r0] = lrow[mt][0];
            g_Pl[pbase + r1] = lrow[mt][1];
        }
    }
}

// ---------------------------------------------------------------------------
// Kernel 3: split-KV merge.
// ---------------------------------------------------------------------------
__global__ __launch_bounds__(256) void merge_kernel(float* __restrict__ out)
{
    int idx = blockIdx.x * 256 + threadIdx.x;      // 0 .. 2M-1
    int d   = idx & 127;
    int row = idx >> 7;                            // b*2048 + n
    float m0 = g_Pm[row], m1 = g_Pm[16384 + row];
    float l0 = g_Pl[row], l1 = g_Pl[16384 + row];
    float m  = fmaxf(m0, m1);
    float e0 = __expf(m0 - m), e1 = __expf(m1 - m);
    float o0 = g_PO[(size_t)row * 128 + d];
    float o1 = g_PO[(size_t)(16384 + row) * 128 + d];
    out[(size_t)row * 128 + d] = (e0 * o0 + e1 * o1) / (e0 * l0 + e1 * l1);
}

// ---------------------------------------------------------------------------
// Launch. Inputs: x, w_q, b_q, w_k, b_k, w_v, b_v (w_q/b_q unused).
// ---------------------------------------------------------------------------
extern "C" void kernel_launch(void* const* d_in, const int* in_sizes, int n_in,
                              void* d_out, int out_size)
{
    const float* x  = (const float*)d_in[0];
    const float* wk = (const float*)d_in[3];
    const float* bk = (const float*)d_in[4];
    const float* wv = (const float*)d_in[5];
    const float* bv = (const float*)d_in[6];
    float* out = (float*)d_out;
    (void)in_sizes; (void)n_in; (void)out_size;

    const int GEMM_SMEM = (128 * 36 + 64 * 36 * 2) * 4;   // 36864 B
    const int ATTN_SMEM = (256 * 128 + 2 * 64 * 128) * 4; // 196608 B
    cudaFuncSetAttribute(kv_gemm_kernel,
                         cudaFuncAttributeMaxDynamicSharedMemorySize, GEMM_SMEM);
    cudaFuncSetAttribute(attn_kernel,
                         cudaFuncAttributeMaxDynamicSharedMemorySize, ATTN_SMEM);

    kv_gemm_kernel<<<dim3(128, 4), 256, GEMM_SMEM>>>(x, wk, bk, wv, bv);
    attn_kernel<<<dim3(8, 2, 8), 256, ATTN_SMEM>>>();
    merge_kernel<<<8192, 256>>>(out);
}

// round 6
// speedup vs baseline: 3.0088x; 1.0817x over previous
#include <cuda_runtime.h>
#include <cuda_bf16.h>
#include <math_constants.h>
#include <cstdint>

// K|V projections: [B*N, 256] fp32(tf32-rounded). K cols 0..127 (pre-scaled by
// softmax_scale*log2e), V cols 128..255.
static __device__ __align__(16) float g_KV[8 * 2048 * 256];
// Split-KV partials: O~ (unnormalized) and l per kv-half.
static __device__ __align__(16) float g_PO[2 * 8 * 2048 * 128];
static __device__ float g_Pl[2 * 8 * 2048];

// ---------------------------------------------------------------------------
// helpers
// ---------------------------------------------------------------------------
__device__ __forceinline__ float tf32_rna(float v) {
    uint32_t r; asm("cvt.rna.tf32.f32 %0, %1;" : "=r"(r) : "f"(v));
    return __uint_as_float(r);
}
__device__ __forceinline__ float ex2(float v) {
    float r; asm("ex2.approx.f32 %0, %1;" : "=f"(r) : "f"(v));
    return r;
}

__device__ __forceinline__ void mma8(float c[4],
                                     uint32_t a0, uint32_t a1, uint32_t a2, uint32_t a3,
                                     uint32_t b0, uint32_t b1) {
    asm volatile(
        "mma.sync.aligned.m16n8k8.row.col.f32.tf32.tf32.f32 "
        "{%0,%1,%2,%3}, {%4,%5,%6,%7}, {%8,%9}, {%0,%1,%2,%3};\n"
        : "+f"(c[0]), "+f"(c[1]), "+f"(c[2]), "+f"(c[3])
        : "r"(a0), "r"(a1), "r"(a2), "r"(a3), "r"(b0), "r"(b1));
}

__device__ __forceinline__ void mma16bf(float c[4],
                                        uint32_t a0, uint32_t a1, uint32_t a2, uint32_t a3,
                                        uint32_t b0, uint32_t b1) {
    asm volatile(
        "mma.sync.aligned.m16n8k16.row.col.f32.bf16.bf16.f32 "
        "{%0,%1,%2,%3}, {%4,%5,%6,%7}, {%8,%9}, {%0,%1,%2,%3};\n"
        : "+f"(c[0]), "+f"(c[1]), "+f"(c[2]), "+f"(c[3])
        : "r"(a0), "r"(a1), "r"(a2), "r"(a3), "r"(b0), "r"(b1));
}

__device__ __forceinline__ void cp16(uint32_t dst, const float* src) {
    asm volatile("cp.async.cg.shared.global [%0], [%1], 16;\n" :: "r"(dst), "l"(src));
}
__device__ __forceinline__ void cp_commit() { asm volatile("cp.async.commit_group;\n"); }
__device__ __forceinline__ void cp_wait0()  { asm volatile("cp.async.wait_group 0;\n"); }

__device__ __forceinline__ uint32_t smem_u32(const void* p) {
    return (uint32_t)__cvta_generic_to_shared(p);
}

// split two fp32 into packed bf16x2 hi + lo (residual) words
__device__ __forceinline__ void split2(float x, float y, uint32_t& h, uint32_t& l) {
    __nv_bfloat16 hx = __float2bfloat16_rn(x);
    __nv_bfloat16 hy = __float2bfloat16_rn(y);
    __nv_bfloat16 lx = __float2bfloat16_rn(x - __bfloat162float(hx));
    __nv_bfloat16 ly = __float2bfloat16_rn(y - __bfloat162float(hy));
    __nv_bfloat162 hp(hx, hy), lp(lx, ly);
    h = *reinterpret_cast<uint32_t*>(&hp);
    l = *reinterpret_cast<uint32_t*>(&lp);
}

// attn XOR swizzle (fp32 tiles, 128-float rows)
#define SWI(r, c) ((r) * 128 + ((c) ^ (((r) & 7) << 2)))

// ---------------------------------------------------------------------------
// Kernel 1: KV projection, bf16 3-pass (hh + hl + lh) tensor-core GEMM.
//   C[16384 x 256] = X[16384 x 1024] . W^T + bias,  W = [w_k ; w_v]
// Block tile 128x64, BK=32, 8 warps (4m x 2n), warp tile 32x32, k16 mma.
// K-columns additionally scaled by 1/sqrt(128)*log2(e) for ex2-softmax.
// ---------------------------------------------------------------------------
__global__ __launch_bounds__(256, 2) void kv_gemm_kernel(
    const float* __restrict__ x,
    const float* __restrict__ wk, const float* __restrict__ bk,
    const float* __restrict__ wv, const float* __restrict__ bv)
{
    constexpr int PITCH = 20;               // u32 per row: 16 data (32 bf16) + 4 pad
    extern __shared__ uint32_t su[];
    uint32_t* Xh = su;                      // 128*20
    uint32_t* Xl = Xh + 128 * PITCH;
    uint32_t* Wh = Xl + 128 * PITCH;        // 64*20
    uint32_t* Wl = Wh + 64 * PITCH;

    const int m0 = blockIdx.x * 128;
    const int j0 = blockIdx.y * 64;
    const int tid  = threadIdx.x;
    const int lane = tid & 31;
    const int w    = tid >> 5;
    const int wm   = w & 3;
    const int wn   = w >> 2;
    const int g    = lane >> 2;
    const int t    = lane & 3;

    float4 px[4], pw[2];
    float acc[2][4][4] = {};

    #pragma unroll
    for (int i = 0; i < 4; ++i) {
        int e = tid + i * 256, r = e >> 3, c4 = e & 7;
        px[i] = *reinterpret_cast<const float4*>(x + (size_t)(m0 + r) * 1024 + c4 * 4);
    }
    #pragma unroll
    for (int i = 0; i < 2; ++i) {
        int e = tid + i * 256, r = e >> 3, c4 = e & 7;
        int j = j0 + r;
        const float* wr = (j < 128) ? wk + (size_t)j * 1024 : wv + (size_t)(j - 128) * 1024;
        pw[i] = *reinterpret_cast<const float4*>(wr + c4 * 4);
    }

    for (int kt = 0; kt < 32; ++kt) {
        __syncthreads();
        #pragma unroll
        for (int i = 0; i < 4; ++i) {
            int e = tid + i * 256, r = e >> 3, c4 = e & 7;
            uint2 H, L;
            split2(px[i].x, px[i].y, H.x, L.x);
            split2(px[i].z, px[i].w, H.y, L.y);
            *reinterpret_cast<uint2*>(Xh + r * PITCH + c4 * 2) = H;
            *reinterpret_cast<uint2*>(Xl + r * PITCH + c4 * 2) = L;
        }
        #pragma unroll
        for (int i = 0; i < 2; ++i) {
            int e = tid + i * 256, r = e >> 3, c4 = e & 7;
            uint2 H, L;
            split2(pw[i].x, pw[i].y, H.x, L.x);
            split2(pw[i].z, pw[i].w, H.y, L.y);
            *reinterpret_cast<uint2*>(Wh + r * PITCH + c4 * 2) = H;
            *reinterpret_cast<uint2*>(Wl + r * PITCH + c4 * 2) = L;
        }
        if (kt < 31) {
            int k0 = (kt + 1) * 32;
            #pragma unroll
            for (int i = 0; i < 4; ++i) {
                int e = tid + i * 256, r = e >> 3, c4 = e & 7;
                px[i] = *reinterpret_cast<const float4*>(x + (size_t)(m0 + r) * 1024 + k0 + c4 * 4);
            }
            #pragma unroll
            for (int i = 0; i < 2; ++i) {
                int e = tid + i * 256, r = e >> 3, c4 = e & 7;
                int j = j0 + r;
                const float* wr = (j < 128) ? wk + (size_t)j * 1024 : wv + (size_t)(j - 128) * 1024;
                pw[i] = *reinterpret_cast<const float4*>(wr + k0 + c4 * 4);
            }
        }
        __syncthreads();

        #pragma unroll
        for (int ks = 0; ks < 2; ++ks) {
            const int kb = ks * 8;              // u32 offset (16 bf16)
            uint32_t ah[2][4], al[2][4];
            #pragma unroll
            for (int mt = 0; mt < 2; ++mt) {
                int rb = wm * 32 + mt * 16;
                ah[mt][0] = Xh[(rb + g    ) * PITCH + kb + t    ];
                ah[mt][1] = Xh[(rb + g + 8) * PITCH + kb + t    ];
                ah[mt][2] = Xh[(rb + g    ) * PITCH + kb + t + 4];
                ah[mt][3] = Xh[(rb + g + 8) * PITCH + kb + t + 4];
                al[mt][0] = Xl[(rb + g    ) * PITCH + kb + t    ];
                al[mt][1] = Xl[(rb + g + 8) * PITCH + kb + t    ];
                al[mt][2] = Xl[(rb + g    ) * PITCH + kb + t + 4];
                al[mt][3] = Xl[(rb + g + 8) * PITCH + kb + t + 4];
            }
            #pragma unroll
            for (int nt = 0; nt < 4; ++nt) {
                int cb = wn * 32 + nt * 8;
                uint32_t bh0 = Wh[(cb + g) * PITCH + kb + t    ];
                uint32_t bh1 = Wh[(cb + g) * PITCH + kb + t + 4];
                uint32_t bl0 = Wl[(cb + g) * PITCH + kb + t    ];
                uint32_t bl1 = Wl[(cb + g) * PITCH + kb + t + 4];
                #pragma unroll
                for (int mt = 0; mt < 2; ++mt) {
                    mma16bf(acc[mt][nt], ah[mt][0], ah[mt][1], ah[mt][2], ah[mt][3], bl0, bl1);
                    mma16bf(acc[mt][nt], al[mt][0], al[mt][1], al[mt][2], al[mt][3], bh0, bh1);
                    mma16bf(acc[mt][nt], ah[mt][0], ah[mt][1], ah[mt][2], ah[mt][3], bh0, bh1);
                }
            }
        }
    }

    // epilogue: + bias, K-cols *= scale*log2e, tf32 round, store
    const float SCL = 0.08838834764831845f * 1.4426950408889634f;
    #pragma unroll
    for (int mt = 0; mt < 2; ++mt) {
        int r0 = m0 + wm * 32 + mt * 16 + g;
        int r1 = r0 + 8;
        #pragma unroll
        for (int nt = 0; nt < 4; ++nt) {
            int col = j0 + wn * 32 + nt * 8 + 2 * t;
            bool isK0 = (col < 128), isK1 = (col + 1 < 128);
            float b0 = isK0 ? bk[col]     : bv[col - 128];
            float b1 = isK1 ? bk[col + 1] : bv[col + 1 - 128];
            float v00 = acc[mt][nt][0] + b0, v01 = acc[mt][nt][1] + b1;
            float v10 = acc[mt][nt][2] + b0, v11 = acc[mt][nt][3] + b1;
            if (isK0) { v00 *= SCL; v10 *= SCL; }
            if (isK1) { v01 *= SCL; v11 *= SCL; }
            float2 o0 = { tf32_rna(v00), tf32_rna(v01) };
            float2 o1 = { tf32_rna(v10), tf32_rna(v11) };
            *reinterpret_cast<float2*>(g_KV + (size_t)r0 * 256 + col) = o0;
            *reinterpret_cast<float2*>(g_KV + (size_t)r1 * 256 + col) = o1;
        }
    }
}

// ---------------------------------------------------------------------------
// Kernel 2: fused flash attention, split-KV x2, max-free ex2 softmax.
// Block: 256 queries, 8 warps (warp = 32 rows = 2 m-tiles), key tiles of 64,
// 1024 keys per CTA. S already in log2 domain (K pre-scaled in gemm).
// ---------------------------------------------------------------------------
__global__ __launch_bounds__(256, 1) void attn_kernel()
{
    extern __shared__ float sm[];
    float* Kq = sm;                         // 256 x 128 (XOR swizzled)
    float* Vb = sm + 256 * 128;             // 2 x 64 x 128 (XOR swizzled)

    const int q0  = blockIdx.x * 256;
    const int kvi = blockIdx.y;             // 0/1
    const int b   = blockIdx.z;
    const int s0  = kvi * 1024;
    const float* KB = g_KV + (size_t)b * 2048 * 256;
    const int tid  = threadIdx.x;
    const int lane = tid & 31;
    const int w    = tid >> 5;
    const int g    = lane >> 2;
    const int t    = lane & 3;

    const uint32_t sKq = smem_u32(Kq);
    const uint32_t sV  = smem_u32(Vb);

    #pragma unroll
    for (int i = 0; i < 32; ++i) {
        int slot = tid + i * 256, r = slot >> 5, c4 = slot & 31;
        cp16(sKq + (uint32_t)SWI(r, c4 * 4) * 4, KB + (size_t)(q0 + r) * 256 + c4 * 4);
    }
    #pragma unroll
    for (int i = 0; i < 8; ++i) {
        int slot = tid + i * 256, r = slot >> 5, c4 = slot & 31;
        cp16(sV + (uint32_t)SWI(r, c4 * 4) * 4, KB + (size_t)(s0 + r) * 256 + 128 + c4 * 4);
    }
    cp_commit();

    float o[2][16][4] = {};
    float psum[2][2] = {};

    const int rb0 = w * 32;

    for (int kt = 0; kt < 16; ++kt) {
        cp_wait0();
        __syncthreads();
        if (kt < 15) {
            int n0 = s0 + (kt + 1) * 64;
            uint32_t dst = sV + (uint32_t)(((kt + 1) & 1) * 64 * 128) * 4;
            #pragma unroll
            for (int i = 0; i < 8; ++i) {
                int slot = tid + i * 256, r = slot >> 5, c4 = slot & 31;
                cp16(dst + (uint32_t)SWI(r, c4 * 4) * 4,
                     KB + (size_t)(n0 + r) * 256 + 128 + c4 * 4);
            }
            cp_commit();
        }
        const float* Vt = Vb + (kt & 1) * 64 * 128;

        // ---- S = Kq . V^T (log2 domain) ----
        float s[2][8][4] = {};
        #pragma unroll
        for (int ks = 0; ks < 16; ++ks) {
            const int k = ks * 8;
            uint32_t a[2][4];
            #pragma unroll
            for (int mt = 0; mt < 2; ++mt) {
                int r0 = rb0 + mt * 16 + g, r1 = r0 + 8;
                a[mt][0] = __float_as_uint(Kq[SWI(r0, k + t    )]);
                a[mt][1] = __float_as_uint(Kq[SWI(r1, k + t    )]);
                a[mt][2] = __float_as_uint(Kq[SWI(r0, k + t + 4)]);
                a[mt][3] = __float_as_uint(Kq[SWI(r1, k + t + 4)]);
            }
            #pragma unroll
            for (int nt = 0; nt < 8; ++nt) {
                int vr = nt * 8 + g;
                uint32_t b0 = __float_as_uint(Vt[SWI(vr, k + t    )]);
                uint32_t b1 = __float_as_uint(Vt[SWI(vr, k + t + 4)]);
                mma8(s[0][nt], a[0][0], a[0][1], a[0][2], a[0][3], b0, b1);
                mma8(s[1][nt], a[1][0], a[1][1], a[1][2], a[1][3], b0, b1);
            }
        }

        // ---- P = ex2(S), accumulate row sums, C-frag -> A-frag via shfl ----
        uint32_t pa[2][8][4];
        const int src0 = (lane & ~3) | (t >> 1);
        const int src1 = src0 + 2;
        #pragma unroll
        for (int mt = 0; mt < 2; ++mt) {
            #pragma unroll
            for (int nt = 0; nt < 8; ++nt) {
                float p0 = ex2(s[mt][nt][0]);
                float p1 = ex2(s[mt][nt][1]);
                float p2 = ex2(s[mt][nt][2]);
                float p3 = ex2(s[mt][nt][3]);
                psum[mt][0] += p0 + p1;
                psum[mt][1] += p2 + p3;
                p0 = tf32_rna(p0); p1 = tf32_rna(p1);
                p2 = tf32_rna(p2); p3 = tf32_rna(p3);
                float x0 = __shfl_sync(0xffffffffu, p0, src0);
                float x1 = __shfl_sync(0xffffffffu, p1, src0);
                float y0 = __shfl_sync(0xffffffffu, p2, src0);
                float y1 = __shfl_sync(0xffffffffu, p3, src0);
                float z0 = __shfl_sync(0xffffffffu, p0, src1);
                float z1 = __shfl_sync(0xffffffffu, p1, src1);
                float u0 = __shfl_sync(0xffffffffu, p2, src1);
                float u1 = __shfl_sync(0xffffffffu, p3, src1);
                pa[mt][nt][0] = __float_as_uint((t & 1) ? x1 : x0);  // (g,   t)
                pa[mt][nt][1] = __float_as_uint((t & 1) ? y1 : y0);  // (g+8, t)
                pa[mt][nt][2] = __float_as_uint((t & 1) ? z1 : z0);  // (g,   t+4)
                pa[mt][nt][3] = __float_as_uint((t & 1) ? u1 : u0);  // (g+8, t+4)
            }
        }

        // ---- O += P . V ----
        #pragma unroll 2
        for (int ks = 0; ks < 8; ++ks) {
            const int k = ks * 8;
            #pragma unroll
            for (int dt = 0; dt < 16; ++dt) {
                int c = dt * 8 + g;
                uint32_t b0 = __float_as_uint(Vt[SWI(k + t,     c)]);
                uint32_t b1 = __float_as_uint(Vt[SWI(k + t + 4, c)]);
                mma8(o[0][dt], pa[0][ks][0], pa[0][ks][1], pa[0][ks][2], pa[0][ks][3], b0, b1);
                mma8(o[1][dt], pa[1][ks][0], pa[1][ks][1], pa[1][ks][2], pa[1][ks][3], b0, b1);
            }
        }
    }

    // ---- epilogue: reduce row sums once, store partial O and l ----
    const size_t pbase = ((size_t)kvi * 8 + b) * 2048 + q0;
    #pragma unroll
    for (int mt = 0; mt < 2; ++mt) {
        float l0 = psum[mt][0], l1 = psum[mt][1];
        l0 += __shfl_xor_sync(0xffffffffu, l0, 1);
        l0 += __shfl_xor_sync(0xffffffffu, l0, 2);
        l1 += __shfl_xor_sync(0xffffffffu, l1, 1);
        l1 += __shfl_xor_sync(0xffffffffu, l1, 2);

        int r0 = rb0 + mt * 16 + g;
        int r1 = r0 + 8;
        float* o0 = g_PO + (pbase + r0) * 128;
        float* o1 = g_PO + (pbase + r1) * 128;
        #pragma unroll
        for (int dt = 0; dt < 16; ++dt) {
            float2 v0 = { o[mt][dt][0], o[mt][dt][1] };
            float2 v1 = { o[mt][dt][2], o[mt][dt][3] };
            *reinterpret_cast<float2*>(o0 + dt * 8 + 2 * t) = v0;
            *reinterpret_cast<float2*>(o1 + dt * 8 + 2 * t) = v1;
        }
        if (t == 0) {
            g_Pl[pbase + r0] = l0;
            g_Pl[pbase + r1] = l1;
        }
    }
}

// ---------------------------------------------------------------------------
// Kernel 3: split-KV merge (no max bookkeeping needed).
// ---------------------------------------------------------------------------
__global__ __launch_bounds__(256) void merge_kernel(float* __restrict__ out)
{
    int idx = blockIdx.x * 256 + threadIdx.x;
    int d   = idx & 127;
    int row = idx >> 7;
    float l0 = g_Pl[row], l1 = g_Pl[16384 + row];
    float o0 = g_PO[(size_t)row * 128 + d];
    float o1 = g_PO[(size_t)(16384 + row) * 128 + d];
    out[(size_t)row * 128 + d] = (o0 + o1) / (l0 + l1);
}

// ---------------------------------------------------------------------------
// Launch. Inputs: x, w_q, b_q, w_k, b_k, w_v, b_v (w_q/b_q unused).
// ---------------------------------------------------------------------------
extern "C" void kernel_launch(void* const* d_in, const int* in_sizes, int n_in,
                              void* d_out, int out_size)
{
    const float* x  = (const float*)d_in[0];
    const float* wk = (const float*)d_in[3];
    const float* bk = (const float*)d_in[4];
    const float* wv = (const float*)d_in[5];
    const float* bv = (const float*)d_in[6];
    float* out = (float*)d_out;
    (void)in_sizes; (void)n_in; (void)out_size;

    const int GEMM_SMEM = (128 * 20 * 2 + 64 * 20 * 2) * 4;   // 30720 B
    const int ATTN_SMEM = (256 * 128 + 2 * 64 * 128) * 4;     // 196608 B
    cudaFuncSetAttribute(kv_gemm_kernel,
                         cudaFuncAttributeMaxDynamicSharedMemorySize, GEMM_SMEM);
    cudaFuncSetAttribute(attn_kernel,
                         cudaFuncAttributeMaxDynamicSharedMemorySize, ATTN_SMEM);

    kv_gemm_kernel<<<dim3(128, 4), 256, GEMM_SMEM>>>(x, wk, bk, wv, bv);
    attn_kernel<<<dim3(8, 2, 8), 256, ATTN_SMEM>>>();
    merge_kernel<<<8192, 256>>>(out);
}

// round 7
// speedup vs baseline: 3.2367x; 1.0758x over previous
#include <cuda_runtime.h>
#include <cuda_fp16.h>
#include <math_constants.h>
#include <cstdint>

// K|V projections, fp16: [B*N, 256]. K cols 0..127 pre-scaled by scale*log2e,
// V cols 128..255.
static __device__ __align__(16) __half g_KV[8 * 2048 * 256];
// Split-KV partials (fp32): O~ (unnormalized) and l per kv-half.
static __device__ __align__(16) float g_PO[2 * 8 * 2048 * 128];
static __device__ float g_Pl[2 * 8 * 2048];

// ---------------------------------------------------------------------------
// helpers
// ---------------------------------------------------------------------------
__device__ __forceinline__ float ex2(float v) {
    float r; asm("ex2.approx.f32 %0, %1;" : "=f"(r) : "f"(v));
    return r;
}

__device__ __forceinline__ void mma16h(float c[4], const uint32_t a[4],
                                       uint32_t b0, uint32_t b1) {
    asm volatile(
        "mma.sync.aligned.m16n8k16.row.col.f32.f16.f16.f32 "
        "{%0,%1,%2,%3}, {%4,%5,%6,%7}, {%8,%9}, {%0,%1,%2,%3};\n"
        : "+f"(c[0]), "+f"(c[1]), "+f"(c[2]), "+f"(c[3])
        : "r"(a[0]), "r"(a[1]), "r"(a[2]), "r"(a[3]), "r"(b0), "r"(b1));
}

__device__ __forceinline__ void ldmx4(uint32_t& r0, uint32_t& r1, uint32_t& r2,
                                      uint32_t& r3, uint32_t addr) {
    asm volatile("ldmatrix.sync.aligned.m8n8.x4.shared.b16 {%0,%1,%2,%3}, [%4];"
                 : "=r"(r0), "=r"(r1), "=r"(r2), "=r"(r3) : "r"(addr));
}
__device__ __forceinline__ void ldmx4t(uint32_t& r0, uint32_t& r1, uint32_t& r2,
                                       uint32_t& r3, uint32_t addr) {
    asm volatile("ldmatrix.sync.aligned.m8n8.x4.trans.shared.b16 {%0,%1,%2,%3}, [%4];"
                 : "=r"(r0), "=r"(r1), "=r"(r2), "=r"(r3) : "r"(addr));
}

__device__ __forceinline__ void cp16(uint32_t dst, const void* src) {
    asm volatile("cp.async.cg.shared.global [%0], [%1], 16;\n" :: "r"(dst), "l"(src));
}
__device__ __forceinline__ void cp_commit() { asm volatile("cp.async.commit_group;\n"); }
__device__ __forceinline__ void cp_wait0()  { asm volatile("cp.async.wait_group 0;\n"); }

__device__ __forceinline__ uint32_t smem_u32(const void* p) {
    return (uint32_t)__cvta_generic_to_shared(p);
}

__device__ __forceinline__ uint32_t h2u(__half2 h) {
    return *reinterpret_cast<uint32_t*>(&h);
}

// ---------------------------------------------------------------------------
// Kernel 1: KV projection, fp16 2-pass (X single-rounded, W hi+lo).
//   C[16384 x 256] = X[16384 x 1024] . W^T + bias,  W = [w_k ; w_v]
// Block tile 128x64, BK=32, 8 warps (4m x 2n), warp tile 32x32, k16 mma.
// K-columns scaled by 1/sqrt(128)*log2(e); output stored fp16.
// smem word layout: 16 data words (32 fp16) + 4 pad per row (PITCH 20).
// ---------------------------------------------------------------------------
__global__ __launch_bounds__(256) void kv_gemm_kernel(
    const float* __restrict__ x,
    const float* __restrict__ wk, const float* __restrict__ bk,
    const float* __restrict__ wv, const float* __restrict__ bv)
{
    constexpr int PITCH = 20;
    __shared__ uint32_t Xs[128 * PITCH];
    __shared__ uint32_t Wh[64 * PITCH];
    __shared__ uint32_t Wl[64 * PITCH];

    const int m0 = blockIdx.x * 128;
    const int j0 = blockIdx.y * 64;
    const int tid  = threadIdx.x;
    const int lane = tid & 31;
    const int w    = tid >> 5;
    const int wm   = w & 3;
    const int wn   = w >> 2;
    const int g    = lane >> 2;
    const int t    = lane & 3;

    float4 px[4], pw[2];
    float acc[2][4][4] = {};

    // prologue fetch (k0 = 0): X 512 slots (8 floats each), W 256 slots
    #pragma unroll
    for (int i = 0; i < 2; ++i) {
        int slot = tid + i * 256, r = slot >> 2, ch = slot & 3;
        const float* src = x + (size_t)(m0 + r) * 1024 + ch * 8;
        px[i * 2]     = *reinterpret_cast<const float4*>(src);
        px[i * 2 + 1] = *reinterpret_cast<const float4*>(src + 4);
    }
    {
        int r = tid >> 2, ch = tid & 3;
        const float* wr = (r < 32 + 32) && (j0 + r < 128) ? wk + (size_t)(j0 + r) * 1024
                                                          : wv + (size_t)(j0 + r - 128) * 1024;
        pw[0] = *reinterpret_cast<const float4*>(wr + ch * 8);
        pw[1] = *reinterpret_cast<const float4*>(wr + ch * 8 + 4);
    }

    for (int kt = 0; kt < 32; ++kt) {
        __syncthreads();
        // store X (single fp16)
        #pragma unroll
        for (int i = 0; i < 2; ++i) {
            int slot = tid + i * 256, r = slot >> 2, ch = slot & 3;
            uint4 H;
            H.x = h2u(__float22half2_rn(make_float2(px[i*2].x,   px[i*2].y)));
            H.y = h2u(__float22half2_rn(make_float2(px[i*2].z,   px[i*2].w)));
            H.z = h2u(__float22half2_rn(make_float2(px[i*2+1].x, px[i*2+1].y)));
            H.w = h2u(__float22half2_rn(make_float2(px[i*2+1].z, px[i*2+1].w)));
            *reinterpret_cast<uint4*>(Xs + r * PITCH + ch * 4) = H;
        }
        // store W hi + lo
        {
            int r = tid >> 2, ch = tid & 3;
            float vv[8] = {pw[0].x, pw[0].y, pw[0].z, pw[0].w,
                           pw[1].x, pw[1].y, pw[1].z, pw[1].w};
            __half hh[8], ll[8];
            #pragma unroll
            for (int e = 0; e < 8; ++e) {
                hh[e] = __float2half_rn(vv[e]);
                ll[e] = __float2half_rn(vv[e] - __half2float(hh[e]));
            }
            uint4 H, L;
            H.x = h2u(__half2(hh[0], hh[1])); H.y = h2u(__half2(hh[2], hh[3]));
            H.z = h2u(__half2(hh[4], hh[5])); H.w = h2u(__half2(hh[6], hh[7]));
            L.x = h2u(__half2(ll[0], ll[1])); L.y = h2u(__half2(ll[2], ll[3]));
            L.z = h2u(__half2(ll[4], ll[5])); L.w = h2u(__half2(ll[6], ll[7]));
            *reinterpret_cast<uint4*>(Wh + r * PITCH + ch * 4) = H;
            *reinterpret_cast<uint4*>(Wl + r * PITCH + ch * 4) = L;
        }
        // prefetch next k-tile
        if (kt < 31) {
            int k0 = (kt + 1) * 32;
            #pragma unroll
            for (int i = 0; i < 2; ++i) {
                int slot = tid + i * 256, r = slot >> 2, ch = slot & 3;
                const float* src = x + (size_t)(m0 + r) * 1024 + k0 + ch * 8;
                px[i * 2]     = *reinterpret_cast<const float4*>(src);
                px[i * 2 + 1] = *reinterpret_cast<const float4*>(src + 4);
            }
            {
                int r = tid >> 2, ch = tid & 3;
                int j = j0 + r;
                const float* wr = (j < 128) ? wk + (size_t)j * 1024 : wv + (size_t)(j - 128) * 1024;
                pw[0] = *reinterpret_cast<const float4*>(wr + k0 + ch * 8);
                pw[1] = *reinterpret_cast<const float4*>(wr + k0 + ch * 8 + 4);
            }
        }
        __syncthreads();

        #pragma unroll
        for (int ks = 0; ks < 2; ++ks) {
            const int kb = ks * 8;
            uint32_t a[2][4];
            #pragma unroll
            for (int mt = 0; mt < 2; ++mt) {
                int rb = wm * 32 + mt * 16;
                a[mt][0] = Xs[(rb + g    ) * PITCH + kb + t    ];
                a[mt][1] = Xs[(rb + g + 8) * PITCH + kb + t    ];
                a[mt][2] = Xs[(rb + g    ) * PITCH + kb + t + 4];
                a[mt][3] = Xs[(rb + g + 8) * PITCH + kb + t + 4];
            }
            #pragma unroll
            for (int nt = 0; nt < 4; ++nt) {
                int cb = wn * 32 + nt * 8;
                uint32_t bh0 = Wh[(cb + g) * PITCH + kb + t    ];
                uint32_t bh1 = Wh[(cb + g) * PITCH + kb + t + 4];
                uint32_t bl0 = Wl[(cb + g) * PITCH + kb + t    ];
                uint32_t bl1 = Wl[(cb + g) * PITCH + kb + t + 4];
                #pragma unroll
                for (int mt = 0; mt < 2; ++mt) {
                    mma16h(acc[mt][nt], a[mt], bl0, bl1);
                    mma16h(acc[mt][nt], a[mt], bh0, bh1);
                }
            }
        }
    }

    // epilogue: + bias, K-cols *= scale*log2e, fp16 store
    const float SCL = 0.08838834764831845f * 1.4426950408889634f;
    #pragma unroll
    for (int mt = 0; mt < 2; ++mt) {
        int r0 = m0 + wm * 32 + mt * 16 + g;
        int r1 = r0 + 8;
        #pragma unroll
        for (int nt = 0; nt < 4; ++nt) {
            int col = j0 + wn * 32 + nt * 8 + 2 * t;
            bool isK = (col < 128);
            float b0 = isK ? bk[col]     : bv[col - 128];
            float b1 = isK ? bk[col + 1] : bv[col + 1 - 128];
            float v00 = acc[mt][nt][0] + b0, v01 = acc[mt][nt][1] + b1;
            float v10 = acc[mt][nt][2] + b0, v11 = acc[mt][nt][3] + b1;
            if (isK) { v00 *= SCL; v01 *= SCL; v10 *= SCL; v11 *= SCL; }
            __half2 h0 = __float22half2_rn(make_float2(v00, v01));
            __half2 h1 = __float22half2_rn(make_float2(v10, v11));
            *reinterpret_cast<__half2*>(g_KV + (size_t)r0 * 256 + col) = h0;
            *reinterpret_cast<__half2*>(g_KV + (size_t)r1 * 256 + col) = h1;
        }
    }
}

// ---------------------------------------------------------------------------
// Kernel 2: fused flash attention, fp16 mma + ldmatrix, split-KV x2,
// max-free ex2 softmax, P reused in registers (C-frag == A-frag layout).
// Block: 256 queries, 8 warps (warp = 32 rows = 2 m-tiles), key tiles of 64.
// smem (words): Kq 256x64, V 2x64x64 (16B-chunk XOR swizzle).
// ---------------------------------------------------------------------------
__global__ __launch_bounds__(256, 1) void attn_kernel()
{
    extern __shared__ uint32_t su[];
    const int q0  = blockIdx.x * 256;
    const int kvi = blockIdx.y;
    const int b   = blockIdx.z;
    const int s0  = kvi * 1024;
    const __half* KB = g_KV + (size_t)b * 2048 * 256;
    const int tid  = threadIdx.x;
    const int lane = tid & 31;
    const int w    = tid >> 5;
    const int g    = lane >> 2;
    const int t    = lane & 3;
    const int mat  = lane >> 3;       // ldmatrix matrix id
    const int mi   = lane & 7;        // row within matrix
    const uint32_t swz = (uint32_t)mi << 2;   // word-level XOR (rows are mod-8 aligned)

    const uint32_t sKq = smem_u32(su);
    const uint32_t sV  = sKq + 16384 * 4;

    // prologue: Kq (256 rows x 16 chunks) + V tile 0 (64 x 16)
    #pragma unroll
    for (int i = 0; i < 16; ++i) {
        int slot = tid + i * 256, r = slot >> 4, ch = slot & 15;
        uint32_t dst = sKq + (uint32_t)(r * 64 + ((ch * 4) ^ ((r & 7) << 2))) * 4;
        cp16(dst, KB + (size_t)(q0 + r) * 256 + ch * 8);
    }
    #pragma unroll
    for (int i = 0; i < 4; ++i) {
        int slot = tid + i * 256, r = slot >> 4, ch = slot & 15;
        uint32_t dst = sV + (uint32_t)(r * 64 + ((ch * 4) ^ ((r & 7) << 2))) * 4;
        cp16(dst, KB + (size_t)(s0 + r) * 256 + 128 + ch * 8);
    }
    cp_commit();

    float o[2][16][4] = {};
    float psum[2][2] = {};
    const int rb0 = w * 32;

    for (int kt = 0; kt < 16; ++kt) {
        cp_wait0();
        __syncthreads();
        if (kt < 15) {
            int n0 = s0 + (kt + 1) * 64;
            uint32_t dstb = sV + (uint32_t)(((kt + 1) & 1) * 4096) * 4;
            #pragma unroll
            for (int i = 0; i < 4; ++i) {
                int slot = tid + i * 256, r = slot >> 4, ch = slot & 15;
                uint32_t dst = dstb + (uint32_t)(r * 64 + ((ch * 4) ^ ((r & 7) << 2))) * 4;
                cp16(dst, KB + (size_t)(n0 + r) * 256 + 128 + ch * 8);
            }
            cp_commit();
        }
        const uint32_t vb = sV + (uint32_t)((kt & 1) * 4096) * 4;

        // ---- S = Kq . V^T (log2 domain, K pre-scaled) ----
        float s[2][8][4] = {};
        #pragma unroll
        for (int ks = 0; ks < 8; ++ks) {
            uint32_t a[2][4];
            #pragma unroll
            for (int mt = 0; mt < 2; ++mt) {
                int row = rb0 + mt * 16 + ((mat & 1) << 3) + mi;
                uint32_t addr = sKq + (uint32_t)(row * 64) * 4
                              + ((((uint32_t)(ks * 2 + (mat >> 1)) * 4) ^ swz) * 4);
                ldmx4(a[mt][0], a[mt][1], a[mt][2], a[mt][3], addr);
            }
            #pragma unroll
            for (int np = 0; np < 4; ++np) {
                int row = np * 16 + ((mat >> 1) << 3) + mi;
                uint32_t addr = vb + (uint32_t)(row * 64) * 4
                              + ((((uint32_t)(ks * 2 + (mat & 1)) * 4) ^ swz) * 4);
                uint32_t b0, b1, b2, b3;
                ldmx4(b0, b1, b2, b3, addr);
                mma16h(s[0][2 * np],     a[0], b0, b1);
                mma16h(s[0][2 * np + 1], a[0], b2, b3);
                mma16h(s[1][2 * np],     a[1], b0, b1);
                mma16h(s[1][2 * np + 1], a[1], b2, b3);
            }
        }

        // ---- P = ex2(S); pack straight into PV A-frags (no shuffles) ----
        uint32_t pa[2][4][4];
        #pragma unroll
        for (int mt = 0; mt < 2; ++mt) {
            #pragma unroll
            for (int nt = 0; nt < 8; ++nt) {
                float p0 = ex2(s[mt][nt][0]);
                float p1 = ex2(s[mt][nt][1]);
                float p2 = ex2(s[mt][nt][2]);
                float p3 = ex2(s[mt][nt][3]);
                psum[mt][0] += p0 + p1;
                psum[mt][1] += p2 + p3;
                uint32_t h01 = h2u(__float22half2_rn(make_float2(p0, p1)));
                uint32_t h23 = h2u(__float22half2_rn(make_float2(p2, p3)));
                int kp = nt >> 1;
                if ((nt & 1) == 0) { pa[mt][kp][0] = h01; pa[mt][kp][1] = h23; }
                else               { pa[mt][kp][2] = h01; pa[mt][kp][3] = h23; }
            }
        }

        // ---- O += P . V  (B via ldmatrix.trans of V[key][d]) ----
        #pragma unroll
        for (int kp = 0; kp < 4; ++kp) {
            #pragma unroll
            for (int dt2 = 0; dt2 < 8; ++dt2) {
                int row = kp * 16 + ((mat & 1) << 3) + mi;
                uint32_t addr = vb + (uint32_t)(row * 64) * 4
                              + ((((uint32_t)(dt2 * 2 + (mat >> 1)) * 4) ^ swz) * 4);
                uint32_t b0, b1, b2, b3;
                ldmx4t(b0, b1, b2, b3, addr);
                mma16h(o[0][dt2 * 2],     pa[0][kp], b0, b1);
                mma16h(o[0][dt2 * 2 + 1], pa[0][kp], b2, b3);
                mma16h(o[1][dt2 * 2],     pa[1][kp], b0, b1);
                mma16h(o[1][dt2 * 2 + 1], pa[1][kp], b2, b3);
            }
        }
    }

    // ---- epilogue: reduce row sums once, store partial O and l ----
    const size_t pbase = ((size_t)kvi * 8 + b) * 2048 + q0;
    #pragma unroll
    for (int mt = 0; mt < 2; ++mt) {
        float l0 = psum[mt][0], l1 = psum[mt][1];
        l0 += __shfl_xor_sync(0xffffffffu, l0, 1);
        l0 += __shfl_xor_sync(0xffffffffu, l0, 2);
        l1 += __shfl_xor_sync(0xffffffffu, l1, 1);
        l1 += __shfl_xor_sync(0xffffffffu, l1, 2);

        int r0 = rb0 + mt * 16 + g;
        int r1 = r0 + 8;
        float* o0 = g_PO + (pbase + r0) * 128;
        float* o1 = g_PO + (pbase + r1) * 128;
        #pragma unroll
        for (int dt = 0; dt < 16; ++dt) {
            float2 v0 = { o[mt][dt][0], o[mt][dt][1] };
            float2 v1 = { o[mt][dt][2], o[mt][dt][3] };
            *reinterpret_cast<float2*>(o0 + dt * 8 + 2 * t) = v0;
            *reinterpret_cast<float2*>(o1 + dt * 8 + 2 * t) = v1;
        }
        if (t == 0) {
            g_Pl[pbase + r0] = l0;
            g_Pl[pbase + r1] = l1;
        }
    }
}

// ---------------------------------------------------------------------------
// Kernel 3: split-KV merge.
// ---------------------------------------------------------------------------
__global__ __launch_bounds__(256) void merge_kernel(float* __restrict__ out)
{
    int idx = blockIdx.x * 256 + threadIdx.x;
    int d   = idx & 127;
    int row = idx >> 7;
    float l0 = g_Pl[row], l1 = g_Pl[16384 + row];
    float o0 = g_PO[(size_t)row * 128 + d];
    float o1 = g_PO[(size_t)(16384 + row) * 128 + d];
    out[(size_t)row * 128 + d] = (o0 + o1) / (l0 + l1);
}

// ---------------------------------------------------------------------------
// Launch. Inputs: x, w_q, b_q, w_k, b_k, w_v, b_v (w_q/b_q unused).
// ---------------------------------------------------------------------------
extern "C" void kernel_launch(void* const* d_in, const int* in_sizes, int n_in,
                              void* d_out, int out_size)
{
    const float* x  = (const float*)d_in[0];
    const float* wk = (const float*)d_in[3];
    const float* bk = (const float*)d_in[4];
    const float* wv = (const float*)d_in[5];
    const float* bv = (const float*)d_in[6];
    float* out = (float*)d_out;
    (void)in_sizes; (void)n_in; (void)out_size;

    const int ATTN_SMEM = (256 * 64 + 2 * 64 * 64) * 4;   // 98304 B
    cudaFuncSetAttribute(attn_kernel,
                         cudaFuncAttributeMaxDynamicSharedMemorySize, ATTN_SMEM);

    kv_gemm_kernel<<<dim3(128, 4), 256>>>(x, wk, bk, wv, bv);
    attn_kernel<<<dim3(8, 2, 8), 256, ATTN_SMEM>>>();
    merge_kernel<<<8192, 256>>>(out);
}

// round 8
// speedup vs baseline: 5.3202x; 1.6437x over previous
#include <cuda_runtime.h>
#include <cuda_fp16.h>
#include <math_constants.h>
#include <cstdint>

// Pre-converted operands.
static __device__ __align__(16) __half g_Xh[16384 * 1024];   // X fp16
static __device__ __align__(16) __half g_Wh[256 * 1024];     // W hi
static __device__ __align__(16) __half g_Wl[256 * 1024];     // W lo (residual)
// K|V projections, fp16: [B*N, 256]. K cols 0..127 pre-scaled by scale*log2e.
static __device__ __align__(16) __half g_KV[8 * 2048 * 256];
// Split-KV partials (fp32).
static __device__ __align__(16) float g_PO[2 * 8 * 2048 * 128];
static __device__ float g_Pl[2 * 8 * 2048];

// ---------------------------------------------------------------------------
// helpers
// ---------------------------------------------------------------------------
__device__ __forceinline__ float ex2(float v) {
    float r; asm("ex2.approx.f32 %0, %1;" : "=f"(r) : "f"(v));
    return r;
}
__device__ __forceinline__ void mma16h(float c[4], const uint32_t a[4],
                                       uint32_t b0, uint32_t b1) {
    asm volatile(
        "mma.sync.aligned.m16n8k16.row.col.f32.f16.f16.f32 "
        "{%0,%1,%2,%3}, {%4,%5,%6,%7}, {%8,%9}, {%0,%1,%2,%3};\n"
        : "+f"(c[0]), "+f"(c[1]), "+f"(c[2]), "+f"(c[3])
        : "r"(a[0]), "r"(a[1]), "r"(a[2]), "r"(a[3]), "r"(b0), "r"(b1));
}
__device__ __forceinline__ void ldmx4(uint32_t& r0, uint32_t& r1, uint32_t& r2,
                                      uint32_t& r3, uint32_t addr) {
    asm volatile("ldmatrix.sync.aligned.m8n8.x4.shared.b16 {%0,%1,%2,%3}, [%4];"
                 : "=r"(r0), "=r"(r1), "=r"(r2), "=r"(r3) : "r"(addr));
}
__device__ __forceinline__ void ldmx4t(uint32_t& r0, uint32_t& r1, uint32_t& r2,
                                       uint32_t& r3, uint32_t addr) {
    asm volatile("ldmatrix.sync.aligned.m8n8.x4.trans.shared.b16 {%0,%1,%2,%3}, [%4];"
                 : "=r"(r0), "=r"(r1), "=r"(r2), "=r"(r3) : "r"(addr));
}
__device__ __forceinline__ void cp16(uint32_t dst, const void* src) {
    asm volatile("cp.async.cg.shared.global [%0], [%1], 16;\n" :: "r"(dst), "l"(src));
}
__device__ __forceinline__ void cp_commit() { asm volatile("cp.async.commit_group;\n"); }
__device__ __forceinline__ void cp_wait0()  { asm volatile("cp.async.wait_group 0;\n"); }
__device__ __forceinline__ void cp_wait1()  { asm volatile("cp.async.wait_group 1;\n"); }

__device__ __forceinline__ uint32_t smem_u32(const void* p) {
    return (uint32_t)__cvta_generic_to_shared(p);
}
__device__ __forceinline__ uint32_t h2u(__half2 h) {
    return *reinterpret_cast<uint32_t*>(&h);
}

// ---------------------------------------------------------------------------
// Kernel 0: convert X -> fp16, W -> fp16 hi/lo.
// ---------------------------------------------------------------------------
__global__ __launch_bounds__(256) void convert_kernel(
    const float* __restrict__ x,
    const float* __restrict__ wk, const float* __restrict__ wv)
{
    const int bid = blockIdx.x;
    const int tid = threadIdx.x;
    if (bid < 8192) {
        size_t base = ((size_t)bid * 256 + tid) * 8;
        float4 v0 = *reinterpret_cast<const float4*>(x + base);
        float4 v1 = *reinterpret_cast<const float4*>(x + base + 4);
        uint4 H;
        H.x = h2u(__float22half2_rn(make_float2(v0.x, v0.y)));
        H.y = h2u(__float22half2_rn(make_float2(v0.z, v0.w)));
        H.z = h2u(__float22half2_rn(make_float2(v1.x, v1.y)));
        H.w = h2u(__float22half2_rn(make_float2(v1.z, v1.w)));
        *reinterpret_cast<uint4*>(g_Xh + base) = H;
    } else {
        int wi = ((bid - 8192) * 256 + tid) * 8;        // 0..262136
        int row = wi >> 10, col = wi & 1023;
        const float* src = (row < 128) ? wk + (size_t)row * 1024 + col
                                       : wv + (size_t)(row - 128) * 1024 + col;
        float4 v0 = *reinterpret_cast<const float4*>(src);
        float4 v1 = *reinterpret_cast<const float4*>(src + 4);
        float vv[8] = {v0.x, v0.y, v0.z, v0.w, v1.x, v1.y, v1.z, v1.w};
        __half hh[8], ll[8];
        #pragma unroll
        for (int e = 0; e < 8; ++e) {
            hh[e] = __float2half_rn(vv[e]);
            ll[e] = __float2half_rn(vv[e] - __half2float(hh[e]));
        }
        uint4 H, L;
        H.x = h2u(__half2(hh[0], hh[1])); H.y = h2u(__half2(hh[2], hh[3]));
        H.z = h2u(__half2(hh[4], hh[5])); H.w = h2u(__half2(hh[6], hh[7]));
        L.x = h2u(__half2(ll[0], ll[1])); L.y = h2u(__half2(ll[2], ll[3]));
        L.z = h2u(__half2(ll[4], ll[5])); L.w = h2u(__half2(ll[6], ll[7]));
        *reinterpret_cast<uint4*>(g_Wh + wi) = H;
        *reinterpret_cast<uint4*>(g_Wl + wi) = L;
    }
}

// ---------------------------------------------------------------------------
// Kernel 1: KV projection, fp16 2-pass, cp.async 3-stage pipeline + ldmatrix.
//   C[16384 x 256] = Xh . (Wh + Wl)^T + bias
// Block tile 128x128, BK=32, 8 warps (4m x 2n), warp tile 32x64.
// smem rows: 16 data words (32 fp16) + 4 pad  (PITCH 20 -> conflict-free).
// ---------------------------------------------------------------------------
static constexpr int GP       = 20;                 // words per smem row
static constexpr int XW_WORDS = 128 * GP;           // 2560 words per operand tile
static constexpr int ST_WORDS = 3 * XW_WORDS;       // X + Wh + Wl per stage
static constexpr int GEMM_SMEM_BYTES = 3 * ST_WORDS * 4;   // 92160

__global__ __launch_bounds__(256, 2) void kv_gemm_kernel(
    const float* __restrict__ bk, const float* __restrict__ bv)
{
    extern __shared__ uint32_t su[];
    const uint32_t sb = smem_u32(su);
    const int m0 = blockIdx.x * 128;
    const int j0 = blockIdx.y * 128;
    const int tid  = threadIdx.x;
    const int lane = tid & 31;
    const int w    = tid >> 5;
    const int wm   = w & 3;
    const int wn   = w >> 2;
    const int g    = lane >> 2;
    const int t    = lane & 3;
    const int mat  = lane >> 3;
    const int mi   = lane & 7;

    auto fill = [&](int stage, int k0) {
        const uint32_t base = sb + (uint32_t)(stage * ST_WORDS) * 4;
        #pragma unroll
        for (int i = 0; i < 2; ++i) {
            int slot = tid + i * 256, r = slot >> 2, c = slot & 3;
            cp16(base + (uint32_t)(r * GP + c * 4) * 4,
                 g_Xh + (size_t)(m0 + r) * 1024 + k0 + c * 8);
        }
        #pragma unroll
        for (int i = 0; i < 2; ++i) {
            int slot = tid + i * 256, r = slot >> 2, c = slot & 3;
            cp16(base + (uint32_t)(XW_WORDS + r * GP + c * 4) * 4,
                 g_Wh + (size_t)(j0 + r) * 1024 + k0 + c * 8);
        }
        #pragma unroll
        for (int i = 0; i < 2; ++i) {
            int slot = tid + i * 256, r = slot >> 2, c = slot & 3;
            cp16(base + (uint32_t)(2 * XW_WORDS + r * GP + c * 4) * 4,
                 g_Wl + (size_t)(j0 + r) * 1024 + k0 + c * 8);
        }
        cp_commit();
    };

    fill(0, 0);
    fill(1, 32);

    float acc[2][8][4] = {};

    for (int kt = 0; kt < 32; ++kt) {
        cp_wait1();
        __syncthreads();
        if (kt + 2 < 32) fill((kt + 2) % 3, (kt + 2) * 32);

        const uint32_t xb  = sb + (uint32_t)((kt % 3) * ST_WORDS) * 4;
        const uint32_t whb = xb + (uint32_t)XW_WORDS * 4;
        const uint32_t wlb = xb + (uint32_t)(2 * XW_WORDS) * 4;

        #pragma unroll
        for (int ks = 0; ks < 2; ++ks) {
            const int kca = ks * 8 + (mat >> 1) * 4;   // A col words
            const int kcb = ks * 8 + (mat & 1) * 4;    // B col words
            uint32_t a[2][4];
            #pragma unroll
            for (int mt = 0; mt < 2; ++mt) {
                int row = wm * 32 + mt * 16 + ((mat & 1) << 3) + mi;
                ldmx4(a[mt][0], a[mt][1], a[mt][2], a[mt][3],
                      xb + (uint32_t)(row * GP + kca) * 4);
            }
            #pragma unroll
            for (int np = 0; np < 4; ++np) {
                int row = wn * 64 + np * 16 + ((mat >> 1) << 3) + mi;
                uint32_t h0, h1, h2, h3, l0, l1, l2, l3;
                ldmx4(h0, h1, h2, h3, whb + (uint32_t)(row * GP + kcb) * 4);
                ldmx4(l0, l1, l2, l3, wlb + (uint32_t)(row * GP + kcb) * 4);
                #pragma unroll
                for (int mt = 0; mt < 2; ++mt) {
                    mma16h(acc[mt][2 * np],     a[mt], l0, l1);
                    mma16h(acc[mt][2 * np],     a[mt], h0, h1);
                    mma16h(acc[mt][2 * np + 1], a[mt], l2, l3);
                    mma16h(acc[mt][2 * np + 1], a[mt], h2, h3);
                }
            }
        }
    }

    // epilogue: + bias, K-cols *= scale*log2e, fp16 store
    const float SCL = 0.08838834764831845f * 1.4426950408889634f;
    #pragma unroll
    for (int mt = 0; mt < 2; ++mt) {
        int r0 = m0 + wm * 32 + mt * 16 + g;
        int r1 = r0 + 8;
        #pragma unroll
        for (int nt = 0; nt < 8; ++nt) {
            int col = j0 + wn * 64 + nt * 8 + 2 * t;
            bool isK = (col < 128);
            float b0 = isK ? bk[col]     : bv[col - 128];
            float b1 = isK ? bk[col + 1] : bv[col + 1 - 128];
            float v00 = acc[mt][nt][0] + b0, v01 = acc[mt][nt][1] + b1;
            float v10 = acc[mt][nt][2] + b0, v11 = acc[mt][nt][3] + b1;
            if (isK) { v00 *= SCL; v01 *= SCL; v10 *= SCL; v11 *= SCL; }
            __half2 h0 = __float22half2_rn(make_float2(v00, v01));
            __half2 h1 = __float22half2_rn(make_float2(v10, v11));
            *reinterpret_cast<__half2*>(g_KV + (size_t)r0 * 256 + col) = h0;
            *reinterpret_cast<__half2*>(g_KV + (size_t)r1 * 256 + col) = h1;
        }
    }
}

// ---------------------------------------------------------------------------
// Kernel 2: fused flash attention (unchanged from R7).
// ---------------------------------------------------------------------------
__global__ __launch_bounds__(256, 1) void attn_kernel()
{
    extern __shared__ uint32_t su[];
    const int q0  = blockIdx.x * 256;
    const int kvi = blockIdx.y;
    const int b   = blockIdx.z;
    const int s0  = kvi * 1024;
    const __half* KB = g_KV + (size_t)b * 2048 * 256;
    const int tid  = threadIdx.x;
    const int lane = tid & 31;
    const int w    = tid >> 5;
    const int g    = lane >> 2;
    const int t    = lane & 3;
    const int mat  = lane >> 3;
    const int mi   = lane & 7;
    const uint32_t swz = (uint32_t)mi << 2;

    const uint32_t sKq = smem_u32(su);
    const uint32_t sV  = sKq + 16384 * 4;

    #pragma unroll
    for (int i = 0; i < 16; ++i) {
        int slot = tid + i * 256, r = slot >> 4, ch = slot & 15;
        uint32_t dst = sKq + (uint32_t)(r * 64 + ((ch * 4) ^ ((r & 7) << 2))) * 4;
        cp16(dst, KB + (size_t)(q0 + r) * 256 + ch * 8);
    }
    #pragma unroll
    for (int i = 0; i < 4; ++i) {
        int slot = tid + i * 256, r = slot >> 4, ch = slot & 15;
        uint32_t dst = sV + (uint32_t)(r * 64 + ((ch * 4) ^ ((r & 7) << 2))) * 4;
        cp16(dst, KB + (size_t)(s0 + r) * 256 + 128 + ch * 8);
    }
    cp_commit();

    float o[2][16][4] = {};
    float psum[2][2] = {};
    const int rb0 = w * 32;

    for (int kt = 0; kt < 16; ++kt) {
        cp_wait0();
        __syncthreads();
        if (kt < 15) {
            int n0 = s0 + (kt + 1) * 64;
            uint32_t dstb = sV + (uint32_t)(((kt + 1) & 1) * 4096) * 4;
            #pragma unroll
            for (int i = 0; i < 4; ++i) {
                int slot = tid + i * 256, r = slot >> 4, ch = slot & 15;
                uint32_t dst = dstb + (uint32_t)(r * 64 + ((ch * 4) ^ ((r & 7) << 2))) * 4;
                cp16(dst, KB + (size_t)(n0 + r) * 256 + 128 + ch * 8);
            }
            cp_commit();
        }
        const uint32_t vb = sV + (uint32_t)((kt & 1) * 4096) * 4;

        float s[2][8][4] = {};
        #pragma unroll
        for (int ks = 0; ks < 8; ++ks) {
            uint32_t a[2][4];
            #pragma unroll
            for (int mt = 0; mt < 2; ++mt) {
                int row = rb0 + mt * 16 + ((mat & 1) << 3) + mi;
                uint32_t addr = sKq + (uint32_t)(row * 64) * 4
                              + ((((uint32_t)(ks * 2 + (mat >> 1)) * 4) ^ swz) * 4);
                ldmx4(a[mt][0], a[mt][1], a[mt][2], a[mt][3], addr);
            }
            #pragma unroll
            for (int np = 0; np < 4; ++np) {
                int row = np * 16 + ((mat >> 1) << 3) + mi;
                uint32_t addr = vb + (uint32_t)(row * 64) * 4
                              + ((((uint32_t)(ks * 2 + (mat & 1)) * 4) ^ swz) * 4);
                uint32_t b0, b1, b2, b3;
                ldmx4(b0, b1, b2, b3, addr);
                mma16h(s[0][2 * np],     a[0], b0, b1);
                mma16h(s[0][2 * np + 1], a[0], b2, b3);
                mma16h(s[1][2 * np],     a[1], b0, b1);
                mma16h(s[1][2 * np + 1], a[1], b2, b3);
            }
        }

        uint32_t pa[2][4][4];
        #pragma unroll
        for (int mt = 0; mt < 2; ++mt) {
            #pragma unroll
            for (int nt = 0; nt < 8; ++nt) {
                float p0 = ex2(s[mt][nt][0]);
                float p1 = ex2(s[mt][nt][1]);
                float p2 = ex2(s[mt][nt][2]);
                float p3 = ex2(s[mt][nt][3]);
                psum[mt][0] += p0 + p1;
                psum[mt][1] += p2 + p3;
                uint32_t h01 = h2u(__float22half2_rn(make_float2(p0, p1)));
                uint32_t h23 = h2u(__float22half2_rn(make_float2(p2, p3)));
                int kp = nt >> 1;
                if ((nt & 1) == 0) { pa[mt][kp][0] = h01; pa[mt][kp][1] = h23; }
                else               { pa[mt][kp][2] = h01; pa[mt][kp][3] = h23; }
            }
        }

        #pragma unroll
        for (int kp = 0; kp < 4; ++kp) {
            #pragma unroll
            for (int dt2 = 0; dt2 < 8; ++dt2) {
                int row = kp * 16 + ((mat & 1) << 3) + mi;
                uint32_t addr = vb + (uint32_t)(row * 64) * 4
                              + ((((uint32_t)(dt2 * 2 + (mat >> 1)) * 4) ^ swz) * 4);
                uint32_t b0, b1, b2, b3;
                ldmx4t(b0, b1, b2, b3, addr);
                mma16h(o[0][dt2 * 2],     pa[0][kp], b0, b1);
                mma16h(o[0][dt2 * 2 + 1], pa[0][kp], b2, b3);
                mma16h(o[1][dt2 * 2],     pa[1][kp], b0, b1);
                mma16h(o[1][dt2 * 2 + 1], pa[1][kp], b2, b3);
            }
        }
    }

    const size_t pbase = ((size_t)kvi * 8 + b) * 2048 + q0;
    #pragma unroll
    for (int mt = 0; mt < 2; ++mt) {
        float l0 = psum[mt][0], l1 = psum[mt][1];
        l0 += __shfl_xor_sync(0xffffffffu, l0, 1);
        l0 += __shfl_xor_sync(0xffffffffu, l0, 2);
        l1 += __shfl_xor_sync(0xffffffffu, l1, 1);
        l1 += __shfl_xor_sync(0xffffffffu, l1, 2);

        int r0 = rb0 + mt * 16 + g;
        int r1 = r0 + 8;
        float* o0 = g_PO + (pbase + r0) * 128;
        float* o1 = g_PO + (pbase + r1) * 128;
        #pragma unroll
        for (int dt = 0; dt < 16; ++dt) {
            float2 v0 = { o[mt][dt][0], o[mt][dt][1] };
            float2 v1 = { o[mt][dt][2], o[mt][dt][3] };
            *reinterpret_cast<float2*>(o0 + dt * 8 + 2 * t) = v0;
            *reinterpret_cast<float2*>(o1 + dt * 8 + 2 * t) = v1;
        }
        if (t == 0) {
            g_Pl[pbase + r0] = l0;
            g_Pl[pbase + r1] = l1;
        }
    }
}

// ---------------------------------------------------------------------------
// Kernel 3: split-KV merge.
// ---------------------------------------------------------------------------
__global__ __launch_bounds__(256) void merge_kernel(float* __restrict__ out)
{
    int idx = blockIdx.x * 256 + threadIdx.x;
    int d   = idx & 127;
    int row = idx >> 7;
    float l0 = g_Pl[row], l1 = g_Pl[16384 + row];
    float o0 = g_PO[(size_t)row * 128 + d];
    float o1 = g_PO[(size_t)(16384 + row) * 128 + d];
    out[(size_t)row * 128 + d] = (o0 + o1) / (l0 + l1);
}

// ---------------------------------------------------------------------------
// Launch. Inputs: x, w_q, b_q, w_k, b_k, w_v, b_v (w_q/b_q unused).
// ---------------------------------------------------------------------------
extern "C" void kernel_launch(void* const* d_in, const int* in_sizes, int n_in,
                              void* d_out, int out_size)
{
    const float* x  = (const float*)d_in[0];
    const float* wk = (const float*)d_in[3];
    const float* bk = (const float*)d_in[4];
    const float* wv = (const float*)d_in[5];
    const float* bv = (const float*)d_in[6];
    float* out = (float*)d_out;
    (void)in_sizes; (void)n_in; (void)out_size;

    const int ATTN_SMEM = (256 * 64 + 2 * 64 * 64) * 4;   // 98304 B
    cudaFuncSetAttribute(kv_gemm_kernel,
                         cudaFuncAttributeMaxDynamicSharedMemorySize, GEMM_SMEM_BYTES);
    cudaFuncSetAttribute(attn_kernel,
                         cudaFuncAttributeMaxDynamicSharedMemorySize, ATTN_SMEM);

    convert_kernel<<<8192 + 128, 256>>>(x, wk, wv);
    kv_gemm_kernel<<<dim3(128, 2), 256, GEMM_SMEM_BYTES>>>(bk, bv);
    attn_kernel<<<dim3(8, 2, 8), 256, ATTN_SMEM>>>();
    merge_kernel<<<8192, 256>>>(out);
}